// round 2
// baseline (speedup 1.0000x reference)
#include <cuda_runtime.h>
#include <math.h>

#define Nn 2048
#define Fd 256
#define Hh 8
#define NH (Nn*Hh)
#define IC 256           // i-chunks for deterministic column-sum partials
#define RPC (Nn/IC)      // 8 rows per chunk
#define SK 4             // split-K for P@v

typedef unsigned long long ull;

// scratch (static device globals: no allocation allowed)
__device__ float g_eq1[NH];       // exp(qk)
__device__ float g_eq2[NH];       // exp(0.2*qk)
__device__ float g_rZ[NH];        // 1/Z[j,h]
__device__ float g_P[Nn*Nn];      // attn_mean (16MB); also overlaid as Z-partials [IC][Nn][Hh]
__device__ float g_PVp[SK*Nn*Fd]; // split-K partials for P@v
__device__ float g_U[Nn*Fd];      // updated nodes
__device__ float g_C[Nn*Nn];      // conn raw
__device__ float g_mu[Nn];
__device__ float g_rs[Nn];

__device__ __forceinline__ void fma2(ull& d, ull a, ull b) {
    asm("fma.rn.f32x2 %0, %1, %2, %3;" : "=l"(d) : "l"(a), "l"(b), "l"(d));
}
__device__ __forceinline__ float2 u2f2(ull v) {
    float2 f;
    asm("mov.b64 {%0,%1}, %2;" : "=f"(f.x), "=f"(f.y) : "l"(v));
    return f;
}

// ---------------- projections: eq1/eq2[N,H], v[N,F] ----------------
__global__ void qkv_kernel(const float* __restrict__ X, const float* __restrict__ Wq,
                           const float* __restrict__ Wk, const float* __restrict__ Wv,
                           float* __restrict__ g_v) {
    __shared__ float xs[Fd];
    int i = blockIdx.x;
    int t = threadIdx.x;
    xs[t] = X[i*Fd + t];
    __syncthreads();
    float acc = 0.f;
    #pragma unroll 8
    for (int c = 0; c < Fd; c++) acc = fmaf(xs[c], Wv[c*Fd + t], acc);
    g_v[i*Fd + t] = acc * 0.0625f;
    int w = t >> 5, lane = t & 31;
    float qa = 0.f, ka = 0.f;
    #pragma unroll
    for (int c = lane; c < Fd; c += 32) {
        float x = xs[c];
        qa = fmaf(x, Wq[c*Hh + w], qa);
        ka = fmaf(x, Wk[c*Hh + w], ka);
    }
    #pragma unroll
    for (int o = 16; o > 0; o >>= 1) {
        qa += __shfl_down_sync(0xffffffffu, qa, o);
        ka += __shfl_down_sync(0xffffffffu, ka, o);
    }
    if (lane == 0) {
        float qk = (qa + ka) * (0.0625f * 0.3535533905932738f);
        g_eq1[i*Hh + w] = __expf(qk);
        g_eq2[i*Hh + w] = __expf(0.2f * qk);
    }
}

// ---------------- pass B: column softmax denominators (partials) ----------------
// exp(leakyrelu(qk+e)) = max(exp(qk)exp(e), exp(.2qk)exp(.2e)); masked -> 0.
__global__ void colz_kernel(const float* __restrict__ bond, const float* __restrict__ dist,
                            const float* __restrict__ deg, const float* __restrict__ pwb,
                            const float* __restrict__ pwbc, const float* __restrict__ pwg) {
    __shared__ float se1[RPC*Hh], se2[RPC*Hh];
    int tid = threadIdx.x;
    int j = blockIdx.x*1024 + tid*4;
    int i0 = blockIdx.y*RPC;
    if (tid < RPC*Hh) { se1[tid] = g_eq1[i0*Hh + tid]; se2[tid] = g_eq2[i0*Hh + tid]; }
    __syncthreads();
    float cb = pwb[0]*pwbc[0], wg = pwg[0];
    float z[4][Hh];
    #pragma unroll
    for (int l = 0; l < 4; l++)
        #pragma unroll
        for (int h = 0; h < Hh; h++) z[l][h] = 0.f;
    #pragma unroll
    for (int ii = 0; ii < RPC; ii++) {
        size_t idx = (size_t)(i0+ii)*Nn + j;
        float4 dg = *(const float4*)&deg[idx];
        float4 bd = *(const float4*)&bond[idx];
        float4 ds = *(const float4*)&dist[idx];
        const float* dgp = &dg.x; const float* bdp = &bd.x; const float* dsp = &ds.x;
        float E1[4], E2[4];
        #pragma unroll
        for (int l = 0; l < 4; l++) {
            float e = fmaf(bdp[l], cb, dsp[l]*wg);
            float f = dgp[l] > 0.f ? 1.f : 0.f;
            E1[l] = __expf(e) * f;
            E2[l] = __expf(0.2f*e) * f;
        }
        #pragma unroll
        for (int l = 0; l < 4; l++)
            #pragma unroll
            for (int h = 0; h < Hh; h++)
                z[l][h] += fmaxf(se1[ii*Hh+h]*E1[l], se2[ii*Hh+h]*E2[l]);
    }
    float* zp = &g_P[(size_t)blockIdx.y*NH + (size_t)j*Hh];
    #pragma unroll
    for (int l = 0; l < 4; l++)
        #pragma unroll
        for (int h = 0; h < Hh; h += 4)
            *(float4*)&zp[l*Hh + h] = make_float4(z[l][h], z[l][h+1], z[l][h+2], z[l][h+3]);
}

__global__ void zred_kernel() {
    int t = blockIdx.x*256 + threadIdx.x;   // < NH
    float s0=0.f, s1=0.f, s2=0.f, s3=0.f, s4=0.f, s5=0.f, s6=0.f, s7=0.f;
    #pragma unroll 4
    for (int c = 0; c < IC; c += 8) {
        s0 += g_P[(size_t)(c+0)*NH + t];
        s1 += g_P[(size_t)(c+1)*NH + t];
        s2 += g_P[(size_t)(c+2)*NH + t];
        s3 += g_P[(size_t)(c+3)*NH + t];
        s4 += g_P[(size_t)(c+4)*NH + t];
        s5 += g_P[(size_t)(c+5)*NH + t];
        s6 += g_P[(size_t)(c+6)*NH + t];
        s7 += g_P[(size_t)(c+7)*NH + t];
    }
    g_rZ[t] = 1.f / (((s0+s1)+(s2+s3)) + ((s4+s5)+(s6+s7)));
}

// ---------------- pass C: P[i,j] = mean_h exp(s)/Z[j,h] ----------------
__global__ void attnp_kernel(const float* __restrict__ bond, const float* __restrict__ dist,
                             const float* __restrict__ deg, const float* __restrict__ pwb,
                             const float* __restrict__ pwbc, const float* __restrict__ pwg) {
    __shared__ float se1[RPC*Hh], se2[RPC*Hh];
    int tid = threadIdx.x;
    int j = blockIdx.x*1024 + tid*4;
    int i0 = blockIdx.y*RPC;
    if (tid < RPC*Hh) { se1[tid] = g_eq1[i0*Hh + tid]; se2[tid] = g_eq2[i0*Hh + tid]; }
    __syncthreads();
    float rz[4][Hh];
    #pragma unroll
    for (int l = 0; l < 4; l++)
        #pragma unroll
        for (int h = 0; h < Hh; h += 4)
            *(float4*)&rz[l][h] = *(const float4*)&g_rZ[(size_t)(j+l)*Hh + h];
    float cb = pwb[0]*pwbc[0], wg = pwg[0];
    #pragma unroll
    for (int ii = 0; ii < RPC; ii++) {
        size_t idx = (size_t)(i0+ii)*Nn + j;
        float4 dg = *(const float4*)&deg[idx];
        float4 bd = *(const float4*)&bond[idx];
        float4 ds = *(const float4*)&dist[idx];
        const float* dgp = &dg.x; const float* bdp = &bd.x; const float* dsp = &ds.x;
        float4 pv;
        float* pvp = &pv.x;
        #pragma unroll
        for (int l = 0; l < 4; l++) {
            float e = fmaf(bdp[l], cb, dsp[l]*wg);
            float f = dgp[l] > 0.f ? 1.f : 0.f;
            float E1 = __expf(e) * f;
            float E2 = __expf(0.2f*e) * f;
            float p = 0.f;
            #pragma unroll
            for (int h = 0; h < Hh; h++)
                p = fmaf(fmaxf(se1[ii*Hh+h]*E1, se2[ii*Hh+h]*E2), rz[l][h], p);
            pvp[l] = p * 0.125f;
        }
        *(float4*)&g_P[idx] = pv;
    }
}

// ---------------- GEMM D: split-K partials of P[N,N] @ v[N,F] ----------------
// BM=64, BN=64, BK=16, 256 threads, 4x4/thread via f32x2. Grid (4, 32, SK).
__global__ void gemm_pv_kernel(const float* __restrict__ g_v) {
    __shared__ float As2[16][128];   // A duplicated: As2[k][2r]=As2[k][2r+1]=A[r][k]
    __shared__ float Bs[16][64];
    int tid = threadIdx.x;
    int bi = blockIdx.y * 64;
    int bc = blockIdx.x * 64;
    int ks = blockIdx.z * (Nn/SK);
    int arow = tid >> 2,  acol = (tid & 3)  << 2;
    int brow = tid >> 4,  bcol = (tid & 15) << 2;
    int ty   = tid >> 4,  tx   = tid & 15;
    ull acc[4][2] = {};
    for (int k0 = ks; k0 < ks + Nn/SK; k0 += 16) {
        float4 a = *(const float4*)&g_P[(size_t)(bi + arow)*Nn + k0 + acol];
        float4 b = *(const float4*)&g_v[(size_t)(k0 + brow)*Fd + bc + bcol];
        *(float2*)&As2[acol+0][2*arow] = make_float2(a.x, a.x);
        *(float2*)&As2[acol+1][2*arow] = make_float2(a.y, a.y);
        *(float2*)&As2[acol+2][2*arow] = make_float2(a.z, a.z);
        *(float2*)&As2[acol+3][2*arow] = make_float2(a.w, a.w);
        *(float4*)&Bs[brow][bcol] = b;
        __syncthreads();
        #pragma unroll
        for (int kk = 0; kk < 16; kk++) {
            ulonglong2 pa0 = *(const ulonglong2*)&As2[kk][ty*8];
            ulonglong2 pa1 = *(const ulonglong2*)&As2[kk][ty*8 + 4];
            ulonglong2 bb  = *(const ulonglong2*)&Bs[kk][tx*4];
            fma2(acc[0][0], pa0.x, bb.x); fma2(acc[0][1], pa0.x, bb.y);
            fma2(acc[1][0], pa0.y, bb.x); fma2(acc[1][1], pa0.y, bb.y);
            fma2(acc[2][0], pa1.x, bb.x); fma2(acc[2][1], pa1.x, bb.y);
            fma2(acc[3][0], pa1.y, bb.x); fma2(acc[3][1], pa1.y, bb.y);
        }
        __syncthreads();
    }
    float* dst = &g_PVp[(size_t)blockIdx.z*Nn*Fd];
    #pragma unroll
    for (int r = 0; r < 4; r++) {
        float2 lo = u2f2(acc[r][0]), hi = u2f2(acc[r][1]);
        *(float4*)&dst[(size_t)(bi + ty*4 + r)*Fd + bc + tx*4] =
            make_float4(lo.x, lo.y, hi.x, hi.y);
    }
}

// reduce split-K partials + elu -> g_U and outU
__global__ void pv_reduce_kernel(float* __restrict__ outU) {
    size_t t4 = ((size_t)blockIdx.x*256 + threadIdx.x) * 4;
    float4 a = *(const float4*)&g_PVp[t4];
    float4 b = *(const float4*)&g_PVp[(size_t)Nn*Fd + t4];
    float4 c = *(const float4*)&g_PVp[(size_t)2*Nn*Fd + t4];
    float4 d = *(const float4*)&g_PVp[(size_t)3*Nn*Fd + t4];
    float4 u;
    float* up = &u.x;
    const float* ap=&a.x; const float* bp=&b.x; const float* cp=&c.x; const float* dp=&d.x;
    #pragma unroll
    for (int l = 0; l < 4; l++) {
        float x = (ap[l]+bp[l]) + (cp[l]+dp[l]);
        up[l] = x > 0.f ? x : expm1f(x);
    }
    *(float4*)&g_U[t4] = u;
    *(float4*)&outU[t4] = u;
}

// ---------------- GEMM E: sim = U U^T, fused conn epilogue ----------------
// BM=BN=128, BK=16, 512 threads, 4x8/thread via f32x2. Grid (16,16).
__global__ void __launch_bounds__(512) simconn_kernel(const float* __restrict__ dist,
                                                      const float* __restrict__ deg) {
    __shared__ float As2[16][256];   // duplicated rows
    __shared__ float Bs[16][128];
    int tid = threadIdx.x;
    int bi = blockIdx.y * 128;
    int bj = blockIdx.x * 128;
    int arow = tid >> 2, acol = (tid & 3) << 2;
    int ty = tid >> 4, tx = tid & 15;   // ty 0..31 (4 rows each), tx 0..15 (8 cols each)
    ull acc[4][4] = {};
    for (int k0 = 0; k0 < Fd; k0 += 16) {
        float4 a = *(const float4*)&g_U[(size_t)(bi + arow)*Fd + k0 + acol];
        float4 b = *(const float4*)&g_U[(size_t)(bj + arow)*Fd + k0 + acol];
        *(float2*)&As2[acol+0][2*arow] = make_float2(a.x, a.x);
        *(float2*)&As2[acol+1][2*arow] = make_float2(a.y, a.y);
        *(float2*)&As2[acol+2][2*arow] = make_float2(a.z, a.z);
        *(float2*)&As2[acol+3][2*arow] = make_float2(a.w, a.w);
        Bs[acol+0][arow] = b.x;
        Bs[acol+1][arow] = b.y;
        Bs[acol+2][arow] = b.z;
        Bs[acol+3][arow] = b.w;
        __syncthreads();
        #pragma unroll
        for (int kk = 0; kk < 16; kk++) {
            ulonglong2 pa0 = *(const ulonglong2*)&As2[kk][ty*8];
            ulonglong2 pa1 = *(const ulonglong2*)&As2[kk][ty*8 + 4];
            ulonglong2 b0  = *(const ulonglong2*)&Bs[kk][tx*8];
            ulonglong2 b1  = *(const ulonglong2*)&Bs[kk][tx*8 + 4];
            fma2(acc[0][0], pa0.x, b0.x); fma2(acc[0][1], pa0.x, b0.y);
            fma2(acc[0][2], pa0.x, b1.x); fma2(acc[0][3], pa0.x, b1.y);
            fma2(acc[1][0], pa0.y, b0.x); fma2(acc[1][1], pa0.y, b0.y);
            fma2(acc[1][2], pa0.y, b1.x); fma2(acc[1][3], pa0.y, b1.y);
            fma2(acc[2][0], pa1.x, b0.x); fma2(acc[2][1], pa1.x, b0.y);
            fma2(acc[2][2], pa1.x, b1.x); fma2(acc[2][3], pa1.x, b1.y);
            fma2(acc[3][0], pa1.y, b0.x); fma2(acc[3][1], pa1.y, b0.y);
            fma2(acc[3][2], pa1.y, b1.x); fma2(acc[3][3], pa1.y, b1.y);
        }
        __syncthreads();
    }
    #pragma unroll
    for (int r = 0; r < 4; r++) {
        size_t irow = (size_t)(bi + ty*4 + r)*Nn;
        size_t idx = irow + bj + tx*8;
        float4 d0 = *(const float4*)&dist[idx];
        float4 d1 = *(const float4*)&dist[idx + 4];
        float4 m0 = *(const float4*)&deg[idx];
        float4 m1 = *(const float4*)&deg[idx + 4];
        float s[8];
        #pragma unroll
        for (int c = 0; c < 4; c++) {
            float2 f = u2f2(acc[r][c]);
            s[2*c] = f.x; s[2*c+1] = f.y;
        }
        const float* dd0=&d0.x; const float* dd1=&d1.x;
        const float* mm0=&m0.x; const float* mm1=&m1.x;
        float4 o0, o1;
        float* o0p=&o0.x; float* o1p=&o1.x;
        #pragma unroll
        for (int c = 0; c < 4; c++) {
            o0p[c] = (1.f/(1.f + __expf(-s[c])))   * (-dd0[c]) * mm0[c];
            o1p[c] = (1.f/(1.f + __expf(-s[c+4]))) * (-dd1[c]) * mm1[c];
        }
        *(float4*)&g_C[idx]     = o0;
        *(float4*)&g_C[idx + 4] = o1;
    }
}

// ---------------- row stats for layernorm ----------------
__global__ void rn_stats_kernel() {
    int i = blockIdx.x;
    int t = threadIdx.x;
    const float* row = &g_C[(size_t)i*Nn];
    float s = 0.f, s2 = 0.f;
    for (int j = t*4; j < Nn; j += 1024) {
        float4 v = *(const float4*)&row[j];
        s += (v.x+v.y)+(v.z+v.w);
        s2 = fmaf(v.x,v.x, fmaf(v.y,v.y, fmaf(v.z,v.z, fmaf(v.w,v.w, s2))));
    }
    __shared__ float sa[8], sb[8];
    int w = t >> 5, lane = t & 31;
    #pragma unroll
    for (int o = 16; o > 0; o >>= 1) {
        s  += __shfl_down_sync(0xffffffffu, s, o);
        s2 += __shfl_down_sync(0xffffffffu, s2, o);
    }
    if (lane == 0) { sa[w] = s; sb[w] = s2; }
    __syncthreads();
    if (t == 0) {
        float ts = 0.f, ts2 = 0.f;
        #pragma unroll
        for (int x = 0; x < 8; x++) { ts += sa[x]; ts2 += sb[x]; }
        float mean = ts * (1.f/Nn);
        float var  = ts2 * (1.f/Nn) - mean*mean;
        g_mu[i] = mean;
        g_rs[i] = rsqrtf(var + 1e-5f);
    }
}

// ---------------- out = norm(C) + norm(C)^T (normalization applied on the fly) ----------------
__global__ void symadd_kernel(float* __restrict__ outC) {
    __shared__ float tsh[32][33];
    int bx = blockIdx.x, by = blockIdx.y;
    int tx = threadIdx.x, ty = threadIdx.y;
    #pragma unroll
    for (int r = 0; r < 32; r += 8)
        tsh[ty + r][tx] = g_C[(size_t)(bx*32 + ty + r)*Nn + by*32 + tx];
    int j = bx*32 + tx;
    float muj = g_mu[j], rsj = g_rs[j];
    __syncthreads();
    #pragma unroll
    for (int r = 0; r < 32; r += 8) {
        int i = by*32 + ty + r;
        float mui = g_mu[i], rsi = g_rs[i];
        float cij = g_C[(size_t)i*Nn + j];
        float cji = tsh[tx][ty + r];
        outC[(size_t)i*Nn + j] = (cij - mui)*rsi + (cji - muj)*rsj;
    }
}

extern "C" void kernel_launch(void* const* d_in, const int* in_sizes, int n_in,
                              void* d_out, int out_size) {
    const float* X    = (const float*)d_in[0];
    const float* dist = (const float*)d_in[1];
    const float* bond = (const float*)d_in[2];
    const float* deg  = (const float*)d_in[4];
    const float* Wq   = (const float*)d_in[5];
    const float* Wk   = (const float*)d_in[6];
    const float* Wv   = (const float*)d_in[7];
    const float* wb   = (const float*)d_in[8];
    const float* wbc  = (const float*)d_in[9];
    const float* wg   = (const float*)d_in[10];
    float* out  = (float*)d_out;
    float* outU = out;
    float* outC = out + Nn*Fd;

    // reuse g_PVp's first Nn*Fd floats as v storage? No — v must persist past gemm_pv staging
    // reads; give v its own slot inside g_PVp tail is unsafe. Use g_U as temp v? g_U written
    // only in pv_reduce, after gemm_pv consumed v. Safe: v lives in g_U until pv_reduce.
    float* g_v = g_U;

    qkv_kernel<<<Nn, 256>>>(X, Wq, Wk, Wv, g_v);
    colz_kernel<<<dim3(2, IC), 256>>>(bond, dist, deg, wb, wbc, wg);
    zred_kernel<<<NH/256, 256>>>();
    attnp_kernel<<<dim3(2, IC), 256>>>(bond, dist, deg, wb, wbc, wg);
    gemm_pv_kernel<<<dim3(Fd/64, Nn/64, SK), 256>>>(g_v);
    pv_reduce_kernel<<<Nn*Fd/1024, 256>>>(outU);   // overwrites g_U with elu'd result
    simconn_kernel<<<dim3(Nn/128, Nn/128), 512>>>(dist, deg);
    rn_stats_kernel<<<Nn, 256>>>();
    symadd_kernel<<<dim3(Nn/32, Nn/32), dim3(32, 8)>>>(outC);
}

// round 3
// speedup vs baseline: 1.8677x; 1.8677x over previous
#include <cuda_runtime.h>
#include <math.h>

#define Nn 2048
#define Fd 256
#define Hh 8
#define NH (Nn*Hh)
#define IC 256           // i-chunks for deterministic column-sum partials
#define RPC (Nn/IC)      // 8 rows per chunk
#define SK 8             // split-K for P@v

// scratch (static device globals: no allocation allowed)
__device__ float g_eq1[NH];       // exp(qk)
__device__ float g_eq2[NH];       // exp(0.2*qk)
__device__ float g_rZ[NH];        // 1/Z[j,h]
__device__ float g_P[Nn*Nn];      // attn_mean (16MB); also overlaid as Z-partials [IC][Nn][Hh]
__device__ float g_PVp[SK*Nn*Fd]; // split-K partials for P@v (16MB)
__device__ float g_U[Nn*Fd];      // v, then updated nodes
__device__ float g_C[Nn*Nn];      // conn raw (16MB)
__device__ float g_mu[Nn];
__device__ float g_rs[Nn];

// ---------------- projections: eq1/eq2[N,H], v[N,F] ----------------
__global__ void qkv_kernel(const float* __restrict__ X, const float* __restrict__ Wq,
                           const float* __restrict__ Wk, const float* __restrict__ Wv,
                           float* __restrict__ g_v) {
    __shared__ float xs[Fd];
    int i = blockIdx.x;
    int t = threadIdx.x;
    xs[t] = X[i*Fd + t];
    __syncthreads();
    float acc = 0.f;
    #pragma unroll 8
    for (int c = 0; c < Fd; c++) acc = fmaf(xs[c], Wv[c*Fd + t], acc);
    g_v[i*Fd + t] = acc * 0.0625f;
    int w = t >> 5, lane = t & 31;
    float qa = 0.f, ka = 0.f;
    #pragma unroll
    for (int c = lane; c < Fd; c += 32) {
        float x = xs[c];
        qa = fmaf(x, Wq[c*Hh + w], qa);
        ka = fmaf(x, Wk[c*Hh + w], ka);
    }
    #pragma unroll
    for (int o = 16; o > 0; o >>= 1) {
        qa += __shfl_down_sync(0xffffffffu, qa, o);
        ka += __shfl_down_sync(0xffffffffu, ka, o);
    }
    if (lane == 0) {
        float qk = (qa + ka) * (0.0625f * 0.3535533905932738f);
        g_eq1[i*Hh + w] = __expf(qk);
        g_eq2[i*Hh + w] = __expf(0.2f * qk);
    }
}

// ---------------- pass B: column softmax denominators (partials) ----------------
// exp(leakyrelu(qk+e)) = max(exp(qk)exp(e), exp(.2qk)exp(.2e)); masked -> 0.
__global__ void colz_kernel(const float* __restrict__ bond, const float* __restrict__ dist,
                            const float* __restrict__ deg, const float* __restrict__ pwb,
                            const float* __restrict__ pwbc, const float* __restrict__ pwg) {
    __shared__ float se1[RPC*Hh], se2[RPC*Hh];
    int tid = threadIdx.x;
    int j = blockIdx.x*1024 + tid*4;
    int i0 = blockIdx.y*RPC;
    if (tid < RPC*Hh) { se1[tid] = g_eq1[i0*Hh + tid]; se2[tid] = g_eq2[i0*Hh + tid]; }
    __syncthreads();
    float cb = pwb[0]*pwbc[0], wg = pwg[0];
    float z[4][Hh];
    #pragma unroll
    for (int l = 0; l < 4; l++)
        #pragma unroll
        for (int h = 0; h < Hh; h++) z[l][h] = 0.f;
    #pragma unroll
    for (int ii = 0; ii < RPC; ii++) {
        size_t idx = (size_t)(i0+ii)*Nn + j;
        float4 dg = *(const float4*)&deg[idx];
        float4 bd = *(const float4*)&bond[idx];
        float4 ds = *(const float4*)&dist[idx];
        const float* dgp = &dg.x; const float* bdp = &bd.x; const float* dsp = &ds.x;
        float E1[4], E2[4];
        #pragma unroll
        for (int l = 0; l < 4; l++) {
            float e = fmaf(bdp[l], cb, dsp[l]*wg);
            float f = dgp[l] > 0.f ? 1.f : 0.f;
            E1[l] = __expf(e) * f;
            E2[l] = __expf(0.2f*e) * f;
        }
        #pragma unroll
        for (int l = 0; l < 4; l++)
            #pragma unroll
            for (int h = 0; h < Hh; h++)
                z[l][h] += fmaxf(se1[ii*Hh+h]*E1[l], se2[ii*Hh+h]*E2[l]);
    }
    float* zp = &g_P[(size_t)blockIdx.y*NH + (size_t)j*Hh];
    #pragma unroll
    for (int l = 0; l < 4; l++)
        #pragma unroll
        for (int h = 0; h < Hh; h += 4)
            *(float4*)&zp[l*Hh + h] = make_float4(z[l][h], z[l][h+1], z[l][h+2], z[l][h+3]);
}

__global__ void zred_kernel() {
    int t = blockIdx.x*256 + threadIdx.x;   // < NH
    float s0=0.f, s1=0.f, s2=0.f, s3=0.f, s4=0.f, s5=0.f, s6=0.f, s7=0.f;
    #pragma unroll 4
    for (int c = 0; c < IC; c += 8) {
        s0 += g_P[(size_t)(c+0)*NH + t];
        s1 += g_P[(size_t)(c+1)*NH + t];
        s2 += g_P[(size_t)(c+2)*NH + t];
        s3 += g_P[(size_t)(c+3)*NH + t];
        s4 += g_P[(size_t)(c+4)*NH + t];
        s5 += g_P[(size_t)(c+5)*NH + t];
        s6 += g_P[(size_t)(c+6)*NH + t];
        s7 += g_P[(size_t)(c+7)*NH + t];
    }
    g_rZ[t] = 1.f / (((s0+s1)+(s2+s3)) + ((s4+s5)+(s6+s7)));
}

// ---------------- pass C: P[i,j] = mean_h exp(s)/Z[j,h] ----------------
__global__ void attnp_kernel(const float* __restrict__ bond, const float* __restrict__ dist,
                             const float* __restrict__ deg, const float* __restrict__ pwb,
                             const float* __restrict__ pwbc, const float* __restrict__ pwg) {
    __shared__ float se1[RPC*Hh], se2[RPC*Hh];
    int tid = threadIdx.x;
    int j = blockIdx.x*1024 + tid*4;
    int i0 = blockIdx.y*RPC;
    if (tid < RPC*Hh) { se1[tid] = g_eq1[i0*Hh + tid]; se2[tid] = g_eq2[i0*Hh + tid]; }
    __syncthreads();
    float rz[4][Hh];
    #pragma unroll
    for (int l = 0; l < 4; l++)
        #pragma unroll
        for (int h = 0; h < Hh; h += 4)
            *(float4*)&rz[l][h] = *(const float4*)&g_rZ[(size_t)(j+l)*Hh + h];
    float cb = pwb[0]*pwbc[0], wg = pwg[0];
    #pragma unroll
    for (int ii = 0; ii < RPC; ii++) {
        size_t idx = (size_t)(i0+ii)*Nn + j;
        float4 dg = *(const float4*)&deg[idx];
        float4 bd = *(const float4*)&bond[idx];
        float4 ds = *(const float4*)&dist[idx];
        const float* dgp = &dg.x; const float* bdp = &bd.x; const float* dsp = &ds.x;
        float4 pv;
        float* pvp = &pv.x;
        #pragma unroll
        for (int l = 0; l < 4; l++) {
            float e = fmaf(bdp[l], cb, dsp[l]*wg);
            float f = dgp[l] > 0.f ? 1.f : 0.f;
            float E1 = __expf(e) * f;
            float E2 = __expf(0.2f*e) * f;
            float p = 0.f;
            #pragma unroll
            for (int h = 0; h < Hh; h++)
                p = fmaf(fmaxf(se1[ii*Hh+h]*E1, se2[ii*Hh+h]*E2), rz[l][h], p);
            pvp[l] = p * 0.125f;
        }
        *(float4*)&g_P[idx] = pv;
    }
}

// ---------------- GEMM D: split-K partials of P[N,N] @ v[N,F] ----------------
// BM=128, BN=128, BK=8, 256 threads, 8x8/thread, double-buffered. Grid (2, 16, SK).
__global__ void __launch_bounds__(256) gemm_pv_kernel(const float* __restrict__ g_v) {
    __shared__ float As[2][8][128];
    __shared__ float Bs[2][8][128];
    int tid = threadIdx.x;
    int bi = blockIdx.y * 128;
    int bc = blockIdx.x * 128;
    int ks = blockIdx.z * (Nn/SK);
    const int NT = (Nn/SK)/8;           // 32 k-tiles
    int lr = tid >> 1, lc = (tid & 1) << 2;   // A: 128 rows x 8 cols
    int br = tid >> 5, bc4 = (tid & 31) << 2; // B: 8 rows x 128 cols
    int ty = tid >> 4, tx = tid & 15;
    float acc[8][8] = {};
    // preload tile 0
    {
        float4 a = *(const float4*)&g_P[(size_t)(bi + lr)*Nn + ks + lc];
        float4 b = *(const float4*)&g_v[(size_t)(ks + br)*Fd + bc + bc4];
        As[0][lc+0][lr]=a.x; As[0][lc+1][lr]=a.y; As[0][lc+2][lr]=a.z; As[0][lc+3][lr]=a.w;
        *(float4*)&Bs[0][br][bc4] = b;
    }
    __syncthreads();
    for (int kt = 0; kt < NT; kt++) {
        int cur = kt & 1, nxt = cur ^ 1;
        float4 a, b;
        if (kt + 1 < NT) {
            int k0 = ks + (kt+1)*8;
            a = *(const float4*)&g_P[(size_t)(bi + lr)*Nn + k0 + lc];
            b = *(const float4*)&g_v[(size_t)(k0 + br)*Fd + bc + bc4];
        }
        #pragma unroll
        for (int kk = 0; kk < 8; kk++) {
            float ar[8], brg[8];
            *(float4*)&ar[0]  = *(const float4*)&As[cur][kk][ty*8];
            *(float4*)&ar[4]  = *(const float4*)&As[cur][kk][ty*8+4];
            *(float4*)&brg[0] = *(const float4*)&Bs[cur][kk][tx*8];
            *(float4*)&brg[4] = *(const float4*)&Bs[cur][kk][tx*8+4];
            #pragma unroll
            for (int r = 0; r < 8; r++)
                #pragma unroll
                for (int c = 0; c < 8; c++)
                    acc[r][c] = fmaf(ar[r], brg[c], acc[r][c]);
        }
        if (kt + 1 < NT) {
            As[nxt][lc+0][lr]=a.x; As[nxt][lc+1][lr]=a.y;
            As[nxt][lc+2][lr]=a.z; As[nxt][lc+3][lr]=a.w;
            *(float4*)&Bs[nxt][br][bc4] = b;
        }
        __syncthreads();
    }
    float* dst = &g_PVp[(size_t)blockIdx.z*Nn*Fd];
    #pragma unroll
    for (int r = 0; r < 8; r++) {
        size_t row = (size_t)(bi + ty*8 + r)*Fd + bc + tx*8;
        *(float4*)&dst[row]     = make_float4(acc[r][0], acc[r][1], acc[r][2], acc[r][3]);
        *(float4*)&dst[row + 4] = make_float4(acc[r][4], acc[r][5], acc[r][6], acc[r][7]);
    }
}

// reduce split-K partials + elu -> g_U and outU
__global__ void pv_reduce_kernel(float* __restrict__ outU) {
    size_t t4 = ((size_t)blockIdx.x*256 + threadIdx.x) * 4;
    float s[4] = {0.f, 0.f, 0.f, 0.f};
    #pragma unroll
    for (int p = 0; p < SK; p++) {
        float4 a = *(const float4*)&g_PVp[(size_t)p*Nn*Fd + t4];
        s[0] += a.x; s[1] += a.y; s[2] += a.z; s[3] += a.w;
    }
    float4 u;
    float* up = &u.x;
    #pragma unroll
    for (int l = 0; l < 4; l++)
        up[l] = s[l] > 0.f ? s[l] : expm1f(s[l]);
    *(float4*)&g_U[t4] = u;
    *(float4*)&outU[t4] = u;
}

// ---------------- GEMM E: sim = U U^T (symmetric: upper-triangle blocks only) ----------------
// BM=BN=128, BK=8, 256 threads, 8x8/thread, double-buffered. 136 linear blocks.
__global__ void __launch_bounds__(256) simconn_kernel(const float* __restrict__ dist,
                                                      const float* __restrict__ deg) {
    // map linear block -> (tbi, tbj), tbi <= tbj over 16x16 tiles
    int t = blockIdx.x;
    int tbi = 0;
    while (t >= 16 - tbi) { t -= 16 - tbi; tbi++; }
    int tbj = tbi + t;
    int bi = tbi * 128, bj = tbj * 128;

    __shared__ float As[2][8][128];
    __shared__ float Bs[2][8][128];
    int tid = threadIdx.x;
    int lr = tid >> 1, lc = (tid & 1) << 2;
    int ty = tid >> 4, tx = tid & 15;
    const int NT = Fd/8;   // 32
    float acc[8][8] = {};
    {
        float4 a = *(const float4*)&g_U[(size_t)(bi + lr)*Fd + lc];
        float4 b = *(const float4*)&g_U[(size_t)(bj + lr)*Fd + lc];
        As[0][lc+0][lr]=a.x; As[0][lc+1][lr]=a.y; As[0][lc+2][lr]=a.z; As[0][lc+3][lr]=a.w;
        Bs[0][lc+0][lr]=b.x; Bs[0][lc+1][lr]=b.y; Bs[0][lc+2][lr]=b.z; Bs[0][lc+3][lr]=b.w;
    }
    __syncthreads();
    for (int kt = 0; kt < NT; kt++) {
        int cur = kt & 1, nxt = cur ^ 1;
        float4 a, b;
        if (kt + 1 < NT) {
            int k0 = (kt+1)*8;
            a = *(const float4*)&g_U[(size_t)(bi + lr)*Fd + k0 + lc];
            b = *(const float4*)&g_U[(size_t)(bj + lr)*Fd + k0 + lc];
        }
        #pragma unroll
        for (int kk = 0; kk < 8; kk++) {
            float ar[8], brg[8];
            *(float4*)&ar[0]  = *(const float4*)&As[cur][kk][ty*8];
            *(float4*)&ar[4]  = *(const float4*)&As[cur][kk][ty*8+4];
            *(float4*)&brg[0] = *(const float4*)&Bs[cur][kk][tx*8];
            *(float4*)&brg[4] = *(const float4*)&Bs[cur][kk][tx*8+4];
            #pragma unroll
            for (int r = 0; r < 8; r++)
                #pragma unroll
                for (int c = 0; c < 8; c++)
                    acc[r][c] = fmaf(ar[r], brg[c], acc[r][c]);
        }
        if (kt + 1 < NT) {
            As[nxt][lc+0][lr]=a.x; As[nxt][lc+1][lr]=a.y;
            As[nxt][lc+2][lr]=a.z; As[nxt][lc+3][lr]=a.w;
            Bs[nxt][lc+0][lr]=b.x; Bs[nxt][lc+1][lr]=b.y;
            Bs[nxt][lc+2][lr]=b.z; Bs[nxt][lc+3][lr]=b.w;
        }
        __syncthreads();
    }
    // sigmoid once per element
    float sg[8][8];
    #pragma unroll
    for (int r = 0; r < 8; r++)
        #pragma unroll
        for (int c = 0; c < 8; c++)
            sg[r][c] = 1.f / (1.f + __expf(-acc[r][c]));
    // direct block: C[i,j]
    #pragma unroll
    for (int r = 0; r < 8; r++) {
        size_t idx = (size_t)(bi + ty*8 + r)*Nn + bj + tx*8;
        float4 d0 = *(const float4*)&dist[idx];
        float4 d1 = *(const float4*)&dist[idx + 4];
        float4 m0 = *(const float4*)&deg[idx];
        float4 m1 = *(const float4*)&deg[idx + 4];
        float4 o0 = make_float4(sg[r][0] * (-d0.x) * m0.x, sg[r][1] * (-d0.y) * m0.y,
                                sg[r][2] * (-d0.z) * m0.z, sg[r][3] * (-d0.w) * m0.w);
        float4 o1 = make_float4(sg[r][4] * (-d1.x) * m1.x, sg[r][5] * (-d1.y) * m1.y,
                                sg[r][6] * (-d1.z) * m1.z, sg[r][7] * (-d1.w) * m1.w);
        *(float4*)&g_C[idx]     = o0;
        *(float4*)&g_C[idx + 4] = o1;
    }
    // mirror block: C[j,i] (skip when diagonal)
    if (tbi != tbj) {
        #pragma unroll
        for (int c = 0; c < 8; c++) {
            size_t idx = (size_t)(bj + tx*8 + c)*Nn + bi + ty*8;
            float4 d0 = *(const float4*)&dist[idx];
            float4 d1 = *(const float4*)&dist[idx + 4];
            float4 m0 = *(const float4*)&deg[idx];
            float4 m1 = *(const float4*)&deg[idx + 4];
            float4 o0 = make_float4(sg[0][c] * (-d0.x) * m0.x, sg[1][c] * (-d0.y) * m0.y,
                                    sg[2][c] * (-d0.z) * m0.z, sg[3][c] * (-d0.w) * m0.w);
            float4 o1 = make_float4(sg[4][c] * (-d1.x) * m1.x, sg[5][c] * (-d1.y) * m1.y,
                                    sg[6][c] * (-d1.z) * m1.z, sg[7][c] * (-d1.w) * m1.w);
            *(float4*)&g_C[idx]     = o0;
            *(float4*)&g_C[idx + 4] = o1;
        }
    }
}

// ---------------- row stats for layernorm ----------------
__global__ void rn_stats_kernel() {
    int i = blockIdx.x;
    int t = threadIdx.x;
    const float* row = &g_C[(size_t)i*Nn];
    float s = 0.f, s2 = 0.f;
    for (int j = t*4; j < Nn; j += 1024) {
        float4 v = *(const float4*)&row[j];
        s += (v.x+v.y)+(v.z+v.w);
        s2 = fmaf(v.x,v.x, fmaf(v.y,v.y, fmaf(v.z,v.z, fmaf(v.w,v.w, s2))));
    }
    __shared__ float sa[8], sb[8];
    int w = t >> 5, lane = t & 31;
    #pragma unroll
    for (int o = 16; o > 0; o >>= 1) {
        s  += __shfl_down_sync(0xffffffffu, s, o);
        s2 += __shfl_down_sync(0xffffffffu, s2, o);
    }
    if (lane == 0) { sa[w] = s; sb[w] = s2; }
    __syncthreads();
    if (t == 0) {
        float ts = 0.f, ts2 = 0.f;
        #pragma unroll
        for (int x = 0; x < 8; x++) { ts += sa[x]; ts2 += sb[x]; }
        float mean = ts * (1.f/Nn);
        float var  = ts2 * (1.f/Nn) - mean*mean;
        g_mu[i] = mean;
        g_rs[i] = rsqrtf(var + 1e-5f);
    }
}

// ---------------- out = norm(C) + norm(C)^T (normalization applied on the fly) ----------------
__global__ void symadd_kernel(float* __restrict__ outC) {
    __shared__ float tsh[32][33];
    int bx = blockIdx.x, by = blockIdx.y;
    int tx = threadIdx.x, ty = threadIdx.y;
    #pragma unroll
    for (int r = 0; r < 32; r += 8)
        tsh[ty + r][tx] = g_C[(size_t)(bx*32 + ty + r)*Nn + by*32 + tx];
    int j = bx*32 + tx;
    float muj = g_mu[j], rsj = g_rs[j];
    __syncthreads();
    #pragma unroll
    for (int r = 0; r < 32; r += 8) {
        int i = by*32 + ty + r;
        float mui = g_mu[i], rsi = g_rs[i];
        float cij = g_C[(size_t)i*Nn + j];
        float cji = tsh[tx][ty + r];
        outC[(size_t)i*Nn + j] = (cij - mui)*rsi + (cji - muj)*rsj;
    }
}

extern "C" void kernel_launch(void* const* d_in, const int* in_sizes, int n_in,
                              void* d_out, int out_size) {
    const float* X    = (const float*)d_in[0];
    const float* dist = (const float*)d_in[1];
    const float* bond = (const float*)d_in[2];
    const float* deg  = (const float*)d_in[4];
    const float* Wq   = (const float*)d_in[5];
    const float* Wk   = (const float*)d_in[6];
    const float* Wv   = (const float*)d_in[7];
    const float* wb   = (const float*)d_in[8];
    const float* wbc  = (const float*)d_in[9];
    const float* wg   = (const float*)d_in[10];
    float* out  = (float*)d_out;
    float* outU = out;
    float* outC = out + Nn*Fd;

    // v lives in g_U until pv_reduce overwrites it (gemm_pv has consumed it by then)
    float* g_v = g_U;

    qkv_kernel<<<Nn, 256>>>(X, Wq, Wk, Wv, g_v);
    colz_kernel<<<dim3(2, IC), 256>>>(bond, dist, deg, wb, wbc, wg);
    zred_kernel<<<NH/256, 256>>>();
    attnp_kernel<<<dim3(2, IC), 256>>>(bond, dist, deg, wb, wbc, wg);
    gemm_pv_kernel<<<dim3(Fd/128, Nn/128, SK), 256>>>(g_v);
    pv_reduce_kernel<<<Nn*Fd/1024, 256>>>(outU);
    simconn_kernel<<<136, 256>>>(dist, deg);
    rn_stats_kernel<<<Nn, 256>>>();
    symadd_kernel<<<dim3(Nn/32, Nn/32), dim3(32, 8)>>>(outC);
}

// round 5
// speedup vs baseline: 3.4874x; 1.8672x over previous
#include <cuda_runtime.h>
#include <cuda_bf16.h>
#include <math.h>
#include <stdint.h>

#define Nn 2048
#define Fd 256
#define Hh 8
#define NH (Nn*Hh)
#define IC 256           // i-chunks for deterministic column-sum partials
#define RPC (Nn/IC)      // 8 rows per chunk
#define SK 8             // split-K for P@v
#define BK 32

// ---------------- scratch (static device globals) ----------------
__device__ float g_eq1[NH];
__device__ float g_eq2[NH];
__device__ float g_rZ[NH];
__device__ float g_P[Nn*Nn];                           // Z-partials scratch
__device__ __align__(16) __nv_bfloat16 g_Phi[Nn*Nn];   // P hi [N][N]
__device__ __align__(16) __nv_bfloat16 g_Plo[Nn*Nn];   // P lo
__device__ __align__(16) __nv_bfloat16 g_vThi[Fd*Nn];  // v^T hi [F][N]
__device__ __align__(16) __nv_bfloat16 g_vTlo[Fd*Nn];
__device__ float g_PVp[SK*Nn*Fd];
__device__ float g_U[Nn*Fd];                           // v (fp32), then U
__device__ __align__(16) __nv_bfloat16 g_Uhi[Nn*Fd];   // U hi [N][F]
__device__ __align__(16) __nv_bfloat16 g_Ulo[Nn*Fd];
__device__ float g_C[Nn*Nn];
__device__ float g_mu[Nn];
__device__ float g_rs[Nn];

// ---------------- mma helpers ----------------
__device__ __forceinline__ uint32_t smem_u32(const void* p) {
    uint32_t a;
    asm("{ .reg .u64 t; cvta.to.shared.u64 t, %1; cvt.u32.u64 %0, t; }" : "=r"(a) : "l"(p));
    return a;
}
__device__ __forceinline__ void ldm4(uint32_t* r, uint32_t addr) {
    asm volatile("ldmatrix.sync.aligned.m8n8.x4.shared.b16 {%0,%1,%2,%3}, [%4];"
        : "=r"(r[0]), "=r"(r[1]), "=r"(r[2]), "=r"(r[3]) : "r"(addr));
}
__device__ __forceinline__ void mma16816(float* c, const uint32_t* a, uint32_t b0, uint32_t b1) {
    asm volatile("mma.sync.aligned.m16n8k16.row.col.f32.bf16.bf16.f32 "
        "{%0,%1,%2,%3}, {%4,%5,%6,%7}, {%8,%9}, {%0,%1,%2,%3};"
        : "+f"(c[0]), "+f"(c[1]), "+f"(c[2]), "+f"(c[3])
        : "r"(a[0]), "r"(a[1]), "r"(a[2]), "r"(a[3]), "r"(b0), "r"(b1));
}

// smem tile layout per stage (rows padded to 40 bf16 = 80B for conflict-free ldmatrix)
#define TILE_B   (128*80)         // 10240 bytes per tile
#define OFF_AHI  0
#define OFF_ALO  (TILE_B)
#define OFF_BHI  (2*TILE_B)
#define OFF_BLO  (3*TILE_B)
#define STAGE_B  (4*TILE_B)       // 40960
#define SMEM_MMA (2*STAGE_B)      // 81920 (also >= 128*129*4 staging for sim)

__device__ __forceinline__ void gload2(uint4* d, const __nv_bfloat16* src, int strid, int r, int k) {
    const uint4* p = (const uint4*)(src + (size_t)r*strid + k);
    d[0] = p[0]; d[1] = p[1];
}
__device__ __forceinline__ void sstore2(char* smem, int off, int row, int ch, const uint4* d) {
    uint4* p = (uint4*)(smem + off + row*80 + ch*32);
    p[0] = d[0]; p[1] = d[1];
}

// compute one BK=32 chunk from stage 'base' into acc[2][8][4]
__device__ __forceinline__ void mma_compute(uint32_t base, int mbase, int nbase,
                                            int lane, float acc[2][8][4]) {
    #pragma unroll
    for (int kk = 0; kk < 2; kk++) {
        uint32_t rsel = lane & 15;
        uint32_t csel = (kk*16 + ((lane >> 4) << 3)) * 2;   // byte col offset
        uint32_t ah[2][4], al[2][4], bh[4][4], bl[4][4];
        #pragma unroll
        for (int mt = 0; mt < 2; mt++) {
            uint32_t ro = (mbase + mt*16 + rsel)*80 + csel;
            ldm4(ah[mt], base + OFF_AHI + ro);
            ldm4(al[mt], base + OFF_ALO + ro);
        }
        #pragma unroll
        for (int ck = 0; ck < 4; ck++) {
            uint32_t ro = (nbase + ck*16 + rsel)*80 + csel;
            ldm4(bh[ck], base + OFF_BHI + ro);
            ldm4(bl[ck], base + OFF_BLO + ro);
        }
        #pragma unroll
        for (int mt = 0; mt < 2; mt++)
            #pragma unroll
            for (int nt = 0; nt < 8; nt++) {
                int ck = nt >> 1, pr = nt & 1;
                mma16816(acc[mt][nt], ah[mt], bh[ck][pr], bh[ck][2+pr]);
                mma16816(acc[mt][nt], ah[mt], bl[ck][pr], bl[ck][2+pr]);
                mma16816(acc[mt][nt], al[mt], bh[ck][pr], bh[ck][2+pr]);
            }
    }
}

// ---------------- projections ----------------
__global__ void qkv_kernel(const float* __restrict__ X, const float* __restrict__ Wq,
                           const float* __restrict__ Wk, const float* __restrict__ Wv,
                           float* __restrict__ g_v) {
    __shared__ float xs[Fd];
    int i = blockIdx.x;
    int t = threadIdx.x;
    xs[t] = X[i*Fd + t];
    __syncthreads();
    float acc = 0.f;
    #pragma unroll 8
    for (int c = 0; c < Fd; c++) acc = fmaf(xs[c], Wv[c*Fd + t], acc);
    g_v[i*Fd + t] = acc * 0.0625f;
    int w = t >> 5, lane = t & 31;
    float qa = 0.f, ka = 0.f;
    #pragma unroll
    for (int c = lane; c < Fd; c += 32) {
        float x = xs[c];
        qa = fmaf(x, Wq[c*Hh + w], qa);
        ka = fmaf(x, Wk[c*Hh + w], ka);
    }
    #pragma unroll
    for (int o = 16; o > 0; o >>= 1) {
        qa += __shfl_down_sync(0xffffffffu, qa, o);
        ka += __shfl_down_sync(0xffffffffu, ka, o);
    }
    if (lane == 0) {
        float qk = (qa + ka) * (0.0625f * 0.3535533905932738f);
        g_eq1[i*Hh + w] = __expf(qk);
        g_eq2[i*Hh + w] = __expf(0.2f * qk);
    }
}

// ---------------- v transpose + hi/lo split ----------------
__global__ void vt_kernel(const float* __restrict__ v) {
    __shared__ float t[32][33];
    int i0 = blockIdx.x*32;
    int f0 = blockIdx.y*32;
    int tx = threadIdx.x, ty = threadIdx.y;
    #pragma unroll
    for (int r = 0; r < 32; r += 8)
        t[ty + r][tx] = v[(size_t)(i0 + ty + r)*Fd + f0 + tx];
    __syncthreads();
    #pragma unroll
    for (int r = 0; r < 32; r += 8) {
        int f = f0 + ty + r;
        float x = t[tx][ty + r];
        __nv_bfloat16 hi = __float2bfloat16(x);
        __nv_bfloat16 lo = __float2bfloat16(x - __bfloat162float(hi));
        g_vThi[(size_t)f*Nn + i0 + tx] = hi;
        g_vTlo[(size_t)f*Nn + i0 + tx] = lo;
    }
}

// ---------------- pass B: column softmax denominators ----------------
__global__ void colz_kernel(const float* __restrict__ bond, const float* __restrict__ dist,
                            const float* __restrict__ deg, const float* __restrict__ pwb,
                            const float* __restrict__ pwbc, const float* __restrict__ pwg) {
    __shared__ float se1[RPC*Hh], se2[RPC*Hh];
    int tid = threadIdx.x;
    int j = blockIdx.x*1024 + tid*4;
    int i0 = blockIdx.y*RPC;
    if (tid < RPC*Hh) { se1[tid] = g_eq1[i0*Hh + tid]; se2[tid] = g_eq2[i0*Hh + tid]; }
    __syncthreads();
    float cb = pwb[0]*pwbc[0], wg = pwg[0];
    float z[4][Hh];
    #pragma unroll
    for (int l = 0; l < 4; l++)
        #pragma unroll
        for (int h = 0; h < Hh; h++) z[l][h] = 0.f;
    #pragma unroll
    for (int ii = 0; ii < RPC; ii++) {
        size_t idx = (size_t)(i0+ii)*Nn + j;
        float4 dg = *(const float4*)&deg[idx];
        float4 bd = *(const float4*)&bond[idx];
        float4 ds = *(const float4*)&dist[idx];
        const float* dgp = &dg.x; const float* bdp = &bd.x; const float* dsp = &ds.x;
        float E1[4], E2[4];
        #pragma unroll
        for (int l = 0; l < 4; l++) {
            float e = fmaf(bdp[l], cb, dsp[l]*wg);
            float f = dgp[l] > 0.f ? 1.f : 0.f;
            E1[l] = __expf(e) * f;
            E2[l] = __expf(0.2f*e) * f;
        }
        #pragma unroll
        for (int l = 0; l < 4; l++)
            #pragma unroll
            for (int h = 0; h < Hh; h++)
                z[l][h] += fmaxf(se1[ii*Hh+h]*E1[l], se2[ii*Hh+h]*E2[l]);
    }
    float* zp = &g_P[(size_t)blockIdx.y*NH + (size_t)j*Hh];
    #pragma unroll
    for (int l = 0; l < 4; l++)
        #pragma unroll
        for (int h = 0; h < Hh; h += 4)
            *(float4*)&zp[l*Hh + h] = make_float4(z[l][h], z[l][h+1], z[l][h+2], z[l][h+3]);
}

__global__ void zred_kernel() {
    int t = blockIdx.x*256 + threadIdx.x;
    float s0=0.f,s1=0.f,s2=0.f,s3=0.f,s4=0.f,s5=0.f,s6=0.f,s7=0.f;
    #pragma unroll 4
    for (int c = 0; c < IC; c += 8) {
        s0 += g_P[(size_t)(c+0)*NH + t];
        s1 += g_P[(size_t)(c+1)*NH + t];
        s2 += g_P[(size_t)(c+2)*NH + t];
        s3 += g_P[(size_t)(c+3)*NH + t];
        s4 += g_P[(size_t)(c+4)*NH + t];
        s5 += g_P[(size_t)(c+5)*NH + t];
        s6 += g_P[(size_t)(c+6)*NH + t];
        s7 += g_P[(size_t)(c+7)*NH + t];
    }
    g_rZ[t] = 1.f / (((s0+s1)+(s2+s3)) + ((s4+s5)+(s6+s7)));
}

// ---------------- pass C: P -> bf16 hi/lo ----------------
__global__ void attnp_kernel(const float* __restrict__ bond, const float* __restrict__ dist,
                             const float* __restrict__ deg, const float* __restrict__ pwb,
                             const float* __restrict__ pwbc, const float* __restrict__ pwg) {
    __shared__ float se1[RPC*Hh], se2[RPC*Hh];
    int tid = threadIdx.x;
    int j = blockIdx.x*1024 + tid*4;
    int i0 = blockIdx.y*RPC;
    if (tid < RPC*Hh) { se1[tid] = g_eq1[i0*Hh + tid]; se2[tid] = g_eq2[i0*Hh + tid]; }
    __syncthreads();
    float rz[4][Hh];
    #pragma unroll
    for (int l = 0; l < 4; l++)
        #pragma unroll
        for (int h = 0; h < Hh; h += 4)
            *(float4*)&rz[l][h] = *(const float4*)&g_rZ[(size_t)(j+l)*Hh + h];
    float cb = pwb[0]*pwbc[0], wg = pwg[0];
    #pragma unroll
    for (int ii = 0; ii < RPC; ii++) {
        size_t idx = (size_t)(i0+ii)*Nn + j;
        float4 dg = *(const float4*)&deg[idx];
        float4 bd = *(const float4*)&bond[idx];
        float4 ds = *(const float4*)&dist[idx];
        const float* dgp = &dg.x; const float* bdp = &bd.x; const float* dsp = &ds.x;
        __nv_bfloat16 hi4[4], lo4[4];
        #pragma unroll
        for (int l = 0; l < 4; l++) {
            float e = fmaf(bdp[l], cb, dsp[l]*wg);
            float f = dgp[l] > 0.f ? 1.f : 0.f;
            float E1 = __expf(e) * f;
            float E2 = __expf(0.2f*e) * f;
            float p = 0.f;
            #pragma unroll
            for (int h = 0; h < Hh; h++)
                p = fmaf(fmaxf(se1[ii*Hh+h]*E1, se2[ii*Hh+h]*E2), rz[l][h], p);
            p *= 0.125f;
            hi4[l] = __float2bfloat16(p);
            lo4[l] = __float2bfloat16(p - __bfloat162float(hi4[l]));
        }
        *(uint2*)&g_Phi[idx] = *(uint2*)hi4;
        *(uint2*)&g_Plo[idx] = *(uint2*)lo4;
    }
}

// ---------------- HMMA GEMM: P @ v split-K partials ----------------
// Grid (Fd/128=2, Nn/128=16, SK), 256 threads, 8 warps (4x2), warp tile 32x64.
__global__ void __launch_bounds__(256) gemm_pv_mma() {
    extern __shared__ __align__(128) char smem[];
    uint32_t sb = smem_u32(smem);
    const int tid = threadIdx.x, lane = tid & 31, wid = tid >> 5;
    const int mbase = (wid & 3)*32, nbase = (wid >> 2)*64;
    const int bi = blockIdx.y*128, bc = blockIdx.x*128;
    const int ks = blockIdx.z*(Nn/SK);
    const int NT = (Nn/SK)/BK;   // 8
    const int row = tid >> 1, ch = tid & 1;

    float acc[2][8][4] = {};
    uint4 pA0[2], pA1[2], pB0[2], pB1[2];
    gload2(pA0, g_Phi,  Nn, bi+row, ks + ch*16);
    gload2(pA1, g_Plo,  Nn, bi+row, ks + ch*16);
    gload2(pB0, g_vThi, Nn, bc+row, ks + ch*16);
    gload2(pB1, g_vTlo, Nn, bc+row, ks + ch*16);
    sstore2(smem, OFF_AHI, row, ch, pA0);
    sstore2(smem, OFF_ALO, row, ch, pA1);
    sstore2(smem, OFF_BHI, row, ch, pB0);
    sstore2(smem, OFF_BLO, row, ch, pB1);
    __syncthreads();

    for (int kt = 0; kt < NT; kt++) {
        int cur = kt & 1, nxt = cur ^ 1;
        if (kt + 1 < NT) {
            int k0 = ks + (kt+1)*BK + ch*16;
            gload2(pA0, g_Phi,  Nn, bi+row, k0);
            gload2(pA1, g_Plo,  Nn, bi+row, k0);
            gload2(pB0, g_vThi, Nn, bc+row, k0);
            gload2(pB1, g_vTlo, Nn, bc+row, k0);
        }
        mma_compute(sb + cur*STAGE_B, mbase, nbase, lane, acc);
        if (kt + 1 < NT) {
            sstore2(smem, nxt*STAGE_B + OFF_AHI, row, ch, pA0);
            sstore2(smem, nxt*STAGE_B + OFF_ALO, row, ch, pA1);
            sstore2(smem, nxt*STAGE_B + OFF_BHI, row, ch, pB0);
            sstore2(smem, nxt*STAGE_B + OFF_BLO, row, ch, pB1);
        }
        __syncthreads();
    }
    float* dst = &g_PVp[(size_t)blockIdx.z*Nn*Fd];
    #pragma unroll
    for (int mt = 0; mt < 2; mt++)
        #pragma unroll
        for (int nt = 0; nt < 8; nt++) {
            int r0 = bi + mbase + mt*16 + (lane >> 2);
            int c0 = bc + nbase + nt*8 + (lane & 3)*2;
            *(float2*)&dst[(size_t)r0*Fd + c0]     = make_float2(acc[mt][nt][0], acc[mt][nt][1]);
            *(float2*)&dst[(size_t)(r0+8)*Fd + c0] = make_float2(acc[mt][nt][2], acc[mt][nt][3]);
        }
}

// reduce split-K + elu -> U fp32 (+out) + U hi/lo bf16
__global__ void pv_reduce_kernel(float* __restrict__ outU) {
    size_t t4 = ((size_t)blockIdx.x*256 + threadIdx.x) * 4;
    float s[4] = {0.f, 0.f, 0.f, 0.f};
    #pragma unroll
    for (int p = 0; p < SK; p++) {
        float4 a = *(const float4*)&g_PVp[(size_t)p*Nn*Fd + t4];
        s[0] += a.x; s[1] += a.y; s[2] += a.z; s[3] += a.w;
    }
    float4 u; float* up = &u.x;
    __nv_bfloat16 hi4[4], lo4[4];
    #pragma unroll
    for (int l = 0; l < 4; l++) {
        float x = s[l] > 0.f ? s[l] : expm1f(s[l]);
        up[l] = x;
        hi4[l] = __float2bfloat16(x);
        lo4[l] = __float2bfloat16(x - __bfloat162float(hi4[l]));
    }
    *(float4*)&g_U[t4] = u;
    *(float4*)&outU[t4] = u;
    *(uint2*)&g_Uhi[t4] = *(uint2*)hi4;
    *(uint2*)&g_Ulo[t4] = *(uint2*)lo4;
}

// ---------------- HMMA GEMM: sim = U U^T (upper triangle), fused conn epilogue ----------------
__global__ void __launch_bounds__(256) sim_mma(const float* __restrict__ dist,
                                               const float* __restrict__ deg) {
    int t = blockIdx.x;
    int tbi = 0;
    while (t >= 16 - tbi) { t -= 16 - tbi; tbi++; }
    int tbj = tbi + t;
    int bi = tbi*128, bj = tbj*128;

    extern __shared__ __align__(128) char smem[];
    uint32_t sb = smem_u32(smem);
    const int tid = threadIdx.x, lane = tid & 31, wid = tid >> 5;
    const int mbase = (wid & 3)*32, nbase = (wid >> 2)*64;
    const int NT = Fd/BK;   // 8
    const int row = tid >> 1, ch = tid & 1;

    float acc[2][8][4] = {};
    uint4 pA0[2], pA1[2], pB0[2], pB1[2];
    gload2(pA0, g_Uhi, Fd, bi+row, ch*16);
    gload2(pA1, g_Ulo, Fd, bi+row, ch*16);
    gload2(pB0, g_Uhi, Fd, bj+row, ch*16);
    gload2(pB1, g_Ulo, Fd, bj+row, ch*16);
    sstore2(smem, OFF_AHI, row, ch, pA0);
    sstore2(smem, OFF_ALO, row, ch, pA1);
    sstore2(smem, OFF_BHI, row, ch, pB0);
    sstore2(smem, OFF_BLO, row, ch, pB1);
    __syncthreads();

    for (int kt = 0; kt < NT; kt++) {
        int cur = kt & 1, nxt = cur ^ 1;
        if (kt + 1 < NT) {
            int k0 = (kt+1)*BK + ch*16;
            gload2(pA0, g_Uhi, Fd, bi+row, k0);
            gload2(pA1, g_Ulo, Fd, bi+row, k0);
            gload2(pB0, g_Uhi, Fd, bj+row, k0);
            gload2(pB1, g_Ulo, Fd, bj+row, k0);
        }
        mma_compute(sb + cur*STAGE_B, mbase, nbase, lane, acc);
        if (kt + 1 < NT) {
            sstore2(smem, nxt*STAGE_B + OFF_AHI, row, ch, pA0);
            sstore2(smem, nxt*STAGE_B + OFF_ALO, row, ch, pA1);
            sstore2(smem, nxt*STAGE_B + OFF_BHI, row, ch, pB0);
            sstore2(smem, nxt*STAGE_B + OFF_BLO, row, ch, pB1);
        }
        __syncthreads();
    }

    // stage sigmoid(sim) into smem [128][129] floats (reuses tile space)
    float* st = (float*)smem;
    #pragma unroll
    for (int mt = 0; mt < 2; mt++)
        #pragma unroll
        for (int nt = 0; nt < 8; nt++) {
            int r0 = mbase + mt*16 + (lane >> 2);
            int c0 = nbase + nt*8 + (lane & 3)*2;
            st[r0*129 + c0]       = 1.f / (1.f + __expf(-acc[mt][nt][0]));
            st[r0*129 + c0 + 1]   = 1.f / (1.f + __expf(-acc[mt][nt][1]));
            st[(r0+8)*129 + c0]   = 1.f / (1.f + __expf(-acc[mt][nt][2]));
            st[(r0+8)*129 + c0+1] = 1.f / (1.f + __expf(-acc[mt][nt][3]));
        }
    __syncthreads();
    // direct block C[bi+row, bj+col]
    #pragma unroll
    for (int rep = 0; rep < 8; rep++) {
        int lin = rep*256 + tid;
        int rr = lin >> 4;
        int cb = (lin & 15) << 3;
        size_t idx = (size_t)(bi + rr)*Nn + bj + cb;
        float4 d0 = *(const float4*)&dist[idx];
        float4 d1 = *(const float4*)&dist[idx + 4];
        float4 m0 = *(const float4*)&deg[idx];
        float4 m1 = *(const float4*)&deg[idx + 4];
        const float* sr = &st[rr*129 + cb];
        float4 o0 = make_float4(sr[0]*(-d0.x)*m0.x, sr[1]*(-d0.y)*m0.y,
                                sr[2]*(-d0.z)*m0.z, sr[3]*(-d0.w)*m0.w);
        float4 o1 = make_float4(sr[4]*(-d1.x)*m1.x, sr[5]*(-d1.y)*m1.y,
                                sr[6]*(-d1.z)*m1.z, sr[7]*(-d1.w)*m1.w);
        *(float4*)&g_C[idx]     = o0;
        *(float4*)&g_C[idx + 4] = o1;
    }
    // mirror block C[bj+row, bi+col]
    if (tbi != tbj) {
        #pragma unroll
        for (int rep = 0; rep < 8; rep++) {
            int lin = rep*256 + tid;
            int rr = lin >> 4;
            int cb = (lin & 15) << 3;
            size_t idx = (size_t)(bj + rr)*Nn + bi + cb;
            float4 d0 = *(const float4*)&dist[idx];
            float4 d1 = *(const float4*)&dist[idx + 4];
            float4 m0 = *(const float4*)&deg[idx];
            float4 m1 = *(const float4*)&deg[idx + 4];
            float sv[8];
            #pragma unroll
            for (int k = 0; k < 8; k++) sv[k] = st[(cb + k)*129 + rr];
            float4 o0 = make_float4(sv[0]*(-d0.x)*m0.x, sv[1]*(-d0.y)*m0.y,
                                    sv[2]*(-d0.z)*m0.z, sv[3]*(-d0.w)*m0.w);
            float4 o1 = make_float4(sv[4]*(-d1.x)*m1.x, sv[5]*(-d1.y)*m1.y,
                                    sv[6]*(-d1.z)*m1.z, sv[7]*(-d1.w)*m1.w);
            *(float4*)&g_C[idx]     = o0;
            *(float4*)&g_C[idx + 4] = o1;
        }
    }
}

// ---------------- row stats for layernorm ----------------
__global__ void rn_stats_kernel() {
    int i = blockIdx.x;
    int t = threadIdx.x;
    const float* row = &g_C[(size_t)i*Nn];
    float s = 0.f, s2 = 0.f;
    for (int j = t*4; j < Nn; j += 1024) {
        float4 v = *(const float4*)&row[j];
        s += (v.x+v.y)+(v.z+v.w);
        s2 = fmaf(v.x,v.x, fmaf(v.y,v.y, fmaf(v.z,v.z, fmaf(v.w,v.w, s2))));
    }
    __shared__ float sa[8], sb2[8];
    int w = t >> 5, lane = t & 31;
    #pragma unroll
    for (int o = 16; o > 0; o >>= 1) {
        s  += __shfl_down_sync(0xffffffffu, s, o);
        s2 += __shfl_down_sync(0xffffffffu, s2, o);
    }
    if (lane == 0) { sa[w] = s; sb2[w] = s2; }
    __syncthreads();
    if (t == 0) {
        float ts = 0.f, ts2 = 0.f;
        #pragma unroll
        for (int x = 0; x < 8; x++) { ts += sa[x]; ts2 += sb2[x]; }
        float mean = ts * (1.f/Nn);
        float var  = ts2 * (1.f/Nn) - mean*mean;
        g_mu[i] = mean;
        g_rs[i] = rsqrtf(var + 1e-5f);
    }
}

// ---------------- out = norm(C) + norm(C)^T ----------------
__global__ void symadd_kernel(float* __restrict__ outC) {
    __shared__ float tsh[32][33];
    int bx = blockIdx.x, by = blockIdx.y;
    int tx = threadIdx.x, ty = threadIdx.y;
    #pragma unroll
    for (int r = 0; r < 32; r += 8)
        tsh[ty + r][tx] = g_C[(size_t)(bx*32 + ty + r)*Nn + by*32 + tx];
    int j = bx*32 + tx;
    float muj = g_mu[j], rsj = g_rs[j];
    __syncthreads();
    #pragma unroll
    for (int r = 0; r < 32; r += 8) {
        int i = by*32 + ty + r;
        float mui = g_mu[i], rsi = g_rs[i];
        float cij = g_C[(size_t)i*Nn + j];
        float cji = tsh[tx][ty + r];
        outC[(size_t)i*Nn + j] = (cij - mui)*rsi + (cji - muj)*rsj;
    }
}

extern "C" void kernel_launch(void* const* d_in, const int* in_sizes, int n_in,
                              void* d_out, int out_size) {
    const float* X    = (const float*)d_in[0];
    const float* dist = (const float*)d_in[1];
    const float* bond = (const float*)d_in[2];
    const float* deg  = (const float*)d_in[4];
    const float* Wq   = (const float*)d_in[5];
    const float* Wk   = (const float*)d_in[6];
    const float* Wv   = (const float*)d_in[7];
    const float* wb   = (const float*)d_in[8];
    const float* wbc  = (const float*)d_in[9];
    const float* wg   = (const float*)d_in[10];
    float* out  = (float*)d_out;
    float* outU = out;
    float* outC = out + Nn*Fd;

    cudaFuncSetAttribute(gemm_pv_mma, cudaFuncAttributeMaxDynamicSharedMemorySize, SMEM_MMA);
    cudaFuncSetAttribute(sim_mma, cudaFuncAttributeMaxDynamicSharedMemorySize, SMEM_MMA);

    float* g_v = g_U;   // v lives in g_U until pv_reduce overwrites it

    qkv_kernel<<<Nn, 256>>>(X, Wq, Wk, Wv, g_v);
    vt_kernel<<<dim3(Nn/32, Fd/32), dim3(32, 8)>>>(g_v);
    colz_kernel<<<dim3(2, IC), 256>>>(bond, dist, deg, wb, wbc, wg);
    zred_kernel<<<NH/256, 256>>>();
    attnp_kernel<<<dim3(2, IC), 256>>>(bond, dist, deg, wb, wbc, wg);
    gemm_pv_mma<<<dim3(Fd/128, Nn/128, SK), 256, SMEM_MMA>>>();
    pv_reduce_kernel<<<Nn*Fd/1024, 256>>>(outU);
    sim_mma<<<136, 256, SMEM_MMA>>>(dist, deg);
    rn_stats_kernel<<<Nn, 256>>>();
    symadd_kernel<<<dim3(Nn/32, Nn/32), dim3(32, 8)>>>(outC);
}

// round 6
// speedup vs baseline: 3.5907x; 1.0296x over previous
#include <cuda_runtime.h>
#include <cuda_bf16.h>
#include <math.h>
#include <stdint.h>

#define Nn 2048
#define Fd 256
#define Hh 8
#define NH (Nn*Hh)
#define IC 256           // i-chunks for deterministic column-sum partials
#define RPC (Nn/IC)      // 8 rows per chunk
#define SK 8             // split-K for P@v
#define BK 32

// ---------------- scratch (static device globals) ----------------
__device__ float g_eq1[NH];
__device__ float g_eq2[NH];
__device__ float g_rZ[NH];
__device__ float g_P[Nn*Nn];                           // Z-partials scratch
__device__ __align__(16) __nv_bfloat16 g_Phi[Nn*Nn];   // P hi [N][N]
__device__ __align__(16) __nv_bfloat16 g_Plo[Nn*Nn];   // P lo
__device__ __align__(16) __nv_bfloat16 g_vThi[Fd*Nn];  // v^T hi [F][N]
__device__ __align__(16) __nv_bfloat16 g_vTlo[Fd*Nn];
__device__ float g_PVp[SK*Nn*Fd];                      // split-K partials; also zred scratch
__device__ float g_U[Nn*Fd];                           // v (fp32), then U
__device__ __align__(16) __nv_bfloat16 g_Uhi[Nn*Fd];   // U hi [N][F]
__device__ __align__(16) __nv_bfloat16 g_Ulo[Nn*Fd];
__device__ float g_C[Nn*Nn];
__device__ float g_Sp[16*Nn];                          // LN row-sum partials per col-block
__device__ float g_S2p[16*Nn];
__device__ float g_mu[Nn];
__device__ float g_rs[Nn];

// ---------------- mma helpers ----------------
__device__ __forceinline__ uint32_t smem_u32(const void* p) {
    uint32_t a;
    asm("{ .reg .u64 t; cvta.to.shared.u64 t, %1; cvt.u32.u64 %0, t; }" : "=r"(a) : "l"(p));
    return a;
}
__device__ __forceinline__ void ldm4(uint32_t* r, uint32_t addr) {
    asm volatile("ldmatrix.sync.aligned.m8n8.x4.shared.b16 {%0,%1,%2,%3}, [%4];"
        : "=r"(r[0]), "=r"(r[1]), "=r"(r[2]), "=r"(r[3]) : "r"(addr));
}
__device__ __forceinline__ void mma16816(float* c, const uint32_t* a, uint32_t b0, uint32_t b1) {
    asm volatile("mma.sync.aligned.m16n8k16.row.col.f32.bf16.bf16.f32 "
        "{%0,%1,%2,%3}, {%4,%5,%6,%7}, {%8,%9}, {%0,%1,%2,%3};"
        : "+f"(c[0]), "+f"(c[1]), "+f"(c[2]), "+f"(c[3])
        : "r"(a[0]), "r"(a[1]), "r"(a[2]), "r"(a[3]), "r"(b0), "r"(b1));
}

// smem tile layout per stage (rows padded to 40 bf16 = 80B)
#define TILE_B   (128*80)
#define OFF_AHI  0
#define OFF_ALO  (TILE_B)
#define OFF_BHI  (2*TILE_B)
#define OFF_BLO  (3*TILE_B)
#define STAGE_B  (4*TILE_B)
#define SMEM_MMA (2*STAGE_B)      // 81920 (>= 128*129*4 staging for sim)

__device__ __forceinline__ void gload2(uint4* d, const __nv_bfloat16* src, int strid, int r, int k) {
    const uint4* p = (const uint4*)(src + (size_t)r*strid + k);
    d[0] = p[0]; d[1] = p[1];
}
__device__ __forceinline__ void sstore2(char* smem, int off, int row, int ch, const uint4* d) {
    uint4* p = (uint4*)(smem + off + row*80 + ch*32);
    p[0] = d[0]; p[1] = d[1];
}

__device__ __forceinline__ void mma_compute(uint32_t base, int mbase, int nbase,
                                            int lane, float acc[2][8][4]) {
    #pragma unroll
    for (int kk = 0; kk < 2; kk++) {
        uint32_t rsel = lane & 15;
        uint32_t csel = (kk*16 + ((lane >> 4) << 3)) * 2;
        uint32_t ah[2][4], al[2][4], bh[4][4], bl[4][4];
        #pragma unroll
        for (int mt = 0; mt < 2; mt++) {
            uint32_t ro = (mbase + mt*16 + rsel)*80 + csel;
            ldm4(ah[mt], base + OFF_AHI + ro);
            ldm4(al[mt], base + OFF_ALO + ro);
        }
        #pragma unroll
        for (int ck = 0; ck < 4; ck++) {
            uint32_t ro = (nbase + ck*16 + rsel)*80 + csel;
            ldm4(bh[ck], base + OFF_BHI + ro);
            ldm4(bl[ck], base + OFF_BLO + ro);
        }
        #pragma unroll
        for (int mt = 0; mt < 2; mt++)
            #pragma unroll
            for (int nt = 0; nt < 8; nt++) {
                int ck = nt >> 1, pr = nt & 1;
                mma16816(acc[mt][nt], ah[mt], bh[ck][pr], bh[ck][2+pr]);
                mma16816(acc[mt][nt], ah[mt], bl[ck][pr], bl[ck][2+pr]);
                mma16816(acc[mt][nt], al[mt], bh[ck][pr], bh[ck][2+pr]);
            }
    }
}

// ---------------- qk projection ----------------
__global__ void qk_kernel(const float* __restrict__ X, const float* __restrict__ Wq,
                          const float* __restrict__ Wk) {
    __shared__ float xs[Fd];
    int i = blockIdx.x;
    int t = threadIdx.x;
    xs[t] = X[i*Fd + t];
    __syncthreads();
    int w = t >> 5, lane = t & 31;
    float qa = 0.f, ka = 0.f;
    #pragma unroll
    for (int c = lane; c < Fd; c += 32) {
        float x = xs[c];
        qa = fmaf(x, Wq[c*Hh + w], qa);
        ka = fmaf(x, Wk[c*Hh + w], ka);
    }
    #pragma unroll
    for (int o = 16; o > 0; o >>= 1) {
        qa += __shfl_down_sync(0xffffffffu, qa, o);
        ka += __shfl_down_sync(0xffffffffu, ka, o);
    }
    if (lane == 0) {
        float qk = (qa + ka) * (0.0625f * 0.3535533905932738f);
        g_eq1[i*Hh + w] = __expf(qk);
        g_eq2[i*Hh + w] = __expf(0.2f * qk);
    }
}

// ---------------- v = X @ Wv / 16 (64x64 FFMA tiles) ----------------
__global__ void gemm_v_kernel(const float* __restrict__ X, const float* __restrict__ Wv,
                              float* __restrict__ v) {
    __shared__ float As[16][64];
    __shared__ float Bs[16][64];
    int tid = threadIdx.x;
    int bi = blockIdx.y * 64;
    int bc = blockIdx.x * 64;
    int arow = tid >> 2,  acol = (tid & 3)  << 2;
    int brow = tid >> 4,  bcol = (tid & 15) << 2;
    int ty   = tid >> 4,  tx   = tid & 15;
    float acc[4][4] = {};
    for (int k0 = 0; k0 < Fd; k0 += 16) {
        float4 a = *(const float4*)&X[(size_t)(bi + arow)*Fd + k0 + acol];
        float4 b = *(const float4*)&Wv[(size_t)(k0 + brow)*Fd + bc + bcol];
        As[acol+0][arow] = a.x; As[acol+1][arow] = a.y;
        As[acol+2][arow] = a.z; As[acol+3][arow] = a.w;
        *(float4*)&Bs[brow][bcol] = b;
        __syncthreads();
        #pragma unroll
        for (int kk = 0; kk < 16; kk++) {
            float ar[4], br[4];
            *(float4*)ar = *(const float4*)&As[kk][ty*4];
            *(float4*)br = *(const float4*)&Bs[kk][tx*4];
            #pragma unroll
            for (int r = 0; r < 4; r++)
                #pragma unroll
                for (int c = 0; c < 4; c++)
                    acc[r][c] = fmaf(ar[r], br[c], acc[r][c]);
        }
        __syncthreads();
    }
    #pragma unroll
    for (int r = 0; r < 4; r++) {
        float4 u = make_float4(acc[r][0]*0.0625f, acc[r][1]*0.0625f,
                               acc[r][2]*0.0625f, acc[r][3]*0.0625f);
        *(float4*)&v[(size_t)(bi + ty*4 + r)*Fd + bc + tx*4] = u;
    }
}

// ---------------- v transpose + hi/lo split ----------------
__global__ void vt_kernel(const float* __restrict__ v) {
    __shared__ float t[32][33];
    int i0 = blockIdx.x*32;
    int f0 = blockIdx.y*32;
    int tx = threadIdx.x, ty = threadIdx.y;
    #pragma unroll
    for (int r = 0; r < 32; r += 8)
        t[ty + r][tx] = v[(size_t)(i0 + ty + r)*Fd + f0 + tx];
    __syncthreads();
    #pragma unroll
    for (int r = 0; r < 32; r += 8) {
        int f = f0 + ty + r;
        float x = t[tx][ty + r];
        __nv_bfloat16 hi = __float2bfloat16(x);
        __nv_bfloat16 lo = __float2bfloat16(x - __bfloat162float(hi));
        g_vThi[(size_t)f*Nn + i0 + tx] = hi;
        g_vTlo[(size_t)f*Nn + i0 + tx] = lo;
    }
}

// ---------------- pass B: column softmax denominators ----------------
__global__ void colz_kernel(const float* __restrict__ bond, const float* __restrict__ dist,
                            const float* __restrict__ deg, const float* __restrict__ pwb,
                            const float* __restrict__ pwbc, const float* __restrict__ pwg) {
    __shared__ float2 se[RPC*Hh];
    int tid = threadIdx.x;
    int j = blockIdx.x*1024 + tid*4;
    int i0 = blockIdx.y*RPC;
    if (tid < RPC*Hh) se[tid] = make_float2(g_eq1[i0*Hh + tid], g_eq2[i0*Hh + tid]);
    __syncthreads();
    float cb = pwb[0]*pwbc[0], wg = pwg[0];
    float z[4][Hh];
    #pragma unroll
    for (int l = 0; l < 4; l++)
        #pragma unroll
        for (int h = 0; h < Hh; h++) z[l][h] = 0.f;
    #pragma unroll
    for (int ii = 0; ii < RPC; ii++) {
        size_t idx = (size_t)(i0+ii)*Nn + j;
        float4 dg = *(const float4*)&deg[idx];
        float4 bd = *(const float4*)&bond[idx];
        float4 ds = *(const float4*)&dist[idx];
        const float* dgp = &dg.x; const float* bdp = &bd.x; const float* dsp = &ds.x;
        float E1[4], E2[4];
        #pragma unroll
        for (int l = 0; l < 4; l++) {
            float e = fmaf(bdp[l], cb, dsp[l]*wg);
            float f = dgp[l] > 0.f ? 1.f : 0.f;
            E1[l] = __expf(e) * f;
            E2[l] = __expf(0.2f*e) * f;
        }
        #pragma unroll
        for (int h = 0; h < Hh; h++) {
            float2 s12 = se[ii*Hh + h];
            #pragma unroll
            for (int l = 0; l < 4; l++)
                z[l][h] += fmaxf(s12.x*E1[l], s12.y*E2[l]);
        }
    }
    float* zp = &g_P[(size_t)blockIdx.y*NH + (size_t)j*Hh];
    #pragma unroll
    for (int l = 0; l < 4; l++)
        #pragma unroll
        for (int h = 0; h < Hh; h += 4)
            *(float4*)&zp[l*Hh + h] = make_float4(z[l][h], z[l][h+1], z[l][h+2], z[l][h+3]);
}

// ---------------- zred: two-stage deterministic reduction ----------------
__global__ void zred1_kernel() {
    int t = blockIdx.x*256 + threadIdx.x;   // < NH
    int c0 = blockIdx.y*16;
    float s = 0.f;
    #pragma unroll
    for (int c = 0; c < 16; c++) s += g_P[(size_t)(c0 + c)*NH + t];
    g_PVp[(size_t)blockIdx.y*NH + t] = s;
}
__global__ void zred2_kernel() {
    int t = blockIdx.x*256 + threadIdx.x;   // < NH
    float s = 0.f;
    #pragma unroll
    for (int c = 0; c < 16; c++) s += g_PVp[(size_t)c*NH + t];
    g_rZ[t] = 1.f / s;
}

// ---------------- pass C: P -> bf16 hi/lo ----------------
__global__ void attnp_kernel(const float* __restrict__ bond, const float* __restrict__ dist,
                             const float* __restrict__ deg, const float* __restrict__ pwb,
                             const float* __restrict__ pwbc, const float* __restrict__ pwg) {
    __shared__ float2 se[RPC*Hh];
    int tid = threadIdx.x;
    int j = blockIdx.x*1024 + tid*4;
    int i0 = blockIdx.y*RPC;
    if (tid < RPC*Hh) se[tid] = make_float2(g_eq1[i0*Hh + tid], g_eq2[i0*Hh + tid]);
    __syncthreads();
    float rz[4][Hh];
    #pragma unroll
    for (int l = 0; l < 4; l++)
        #pragma unroll
        for (int h = 0; h < Hh; h += 4)
            *(float4*)&rz[l][h] = *(const float4*)&g_rZ[(size_t)(j+l)*Hh + h];
    float cb = pwb[0]*pwbc[0], wg = pwg[0];
    #pragma unroll
    for (int ii = 0; ii < RPC; ii++) {
        size_t idx = (size_t)(i0+ii)*Nn + j;
        float4 dg = *(const float4*)&deg[idx];
        float4 bd = *(const float4*)&bond[idx];
        float4 ds = *(const float4*)&dist[idx];
        const float* dgp = &dg.x; const float* bdp = &bd.x; const float* dsp = &ds.x;
        float p[4] = {0.f, 0.f, 0.f, 0.f};
        float E1[4], E2[4];
        #pragma unroll
        for (int l = 0; l < 4; l++) {
            float e = fmaf(bdp[l], cb, dsp[l]*wg);
            float f = dgp[l] > 0.f ? 1.f : 0.f;
            E1[l] = __expf(e) * f;
            E2[l] = __expf(0.2f*e) * f;
        }
        #pragma unroll
        for (int h = 0; h < Hh; h++) {
            float2 s12 = se[ii*Hh + h];
            #pragma unroll
            for (int l = 0; l < 4; l++)
                p[l] = fmaf(fmaxf(s12.x*E1[l], s12.y*E2[l]), rz[l][h], p[l]);
        }
        __nv_bfloat16 hi4[4], lo4[4];
        #pragma unroll
        for (int l = 0; l < 4; l++) {
            float pv = p[l] * 0.125f;
            hi4[l] = __float2bfloat16(pv);
            lo4[l] = __float2bfloat16(pv - __bfloat162float(hi4[l]));
        }
        *(uint2*)&g_Phi[idx] = *(uint2*)hi4;
        *(uint2*)&g_Plo[idx] = *(uint2*)lo4;
    }
}

// ---------------- HMMA GEMM: P @ v split-K partials ----------------
__global__ void __launch_bounds__(256) gemm_pv_mma() {
    extern __shared__ __align__(128) char smem[];
    uint32_t sb = smem_u32(smem);
    const int tid = threadIdx.x, lane = tid & 31, wid = tid >> 5;
    const int mbase = (wid & 3)*32, nbase = (wid >> 2)*64;
    const int bi = blockIdx.y*128, bc = blockIdx.x*128;
    const int ks = blockIdx.z*(Nn/SK);
    const int NT = (Nn/SK)/BK;   // 8
    const int row = tid >> 1, ch = tid & 1;

    float acc[2][8][4] = {};
    uint4 pA0[2], pA1[2], pB0[2], pB1[2];
    gload2(pA0, g_Phi,  Nn, bi+row, ks + ch*16);
    gload2(pA1, g_Plo,  Nn, bi+row, ks + ch*16);
    gload2(pB0, g_vThi, Nn, bc+row, ks + ch*16);
    gload2(pB1, g_vTlo, Nn, bc+row, ks + ch*16);
    sstore2(smem, OFF_AHI, row, ch, pA0);
    sstore2(smem, OFF_ALO, row, ch, pA1);
    sstore2(smem, OFF_BHI, row, ch, pB0);
    sstore2(smem, OFF_BLO, row, ch, pB1);
    __syncthreads();

    for (int kt = 0; kt < NT; kt++) {
        int cur = kt & 1, nxt = cur ^ 1;
        if (kt + 1 < NT) {
            int k0 = ks + (kt+1)*BK + ch*16;
            gload2(pA0, g_Phi,  Nn, bi+row, k0);
            gload2(pA1, g_Plo,  Nn, bi+row, k0);
            gload2(pB0, g_vThi, Nn, bc+row, k0);
            gload2(pB1, g_vTlo, Nn, bc+row, k0);
        }
        mma_compute(sb + cur*STAGE_B, mbase, nbase, lane, acc);
        if (kt + 1 < NT) {
            sstore2(smem, nxt*STAGE_B + OFF_AHI, row, ch, pA0);
            sstore2(smem, nxt*STAGE_B + OFF_ALO, row, ch, pA1);
            sstore2(smem, nxt*STAGE_B + OFF_BHI, row, ch, pB0);
            sstore2(smem, nxt*STAGE_B + OFF_BLO, row, ch, pB1);
        }
        __syncthreads();
    }
    float* dst = &g_PVp[(size_t)blockIdx.z*Nn*Fd];
    #pragma unroll
    for (int mt = 0; mt < 2; mt++)
        #pragma unroll
        for (int nt = 0; nt < 8; nt++) {
            int r0 = bi + mbase + mt*16 + (lane >> 2);
            int c0 = bc + nbase + nt*8 + (lane & 3)*2;
            *(float2*)&dst[(size_t)r0*Fd + c0]     = make_float2(acc[mt][nt][0], acc[mt][nt][1]);
            *(float2*)&dst[(size_t)(r0+8)*Fd + c0] = make_float2(acc[mt][nt][2], acc[mt][nt][3]);
        }
}

// reduce split-K + elu -> U fp32 (+out) + U hi/lo bf16
__global__ void pv_reduce_kernel(float* __restrict__ outU) {
    size_t t4 = ((size_t)blockIdx.x*256 + threadIdx.x) * 4;
    float s[4] = {0.f, 0.f, 0.f, 0.f};
    #pragma unroll
    for (int p = 0; p < SK; p++) {
        float4 a = *(const float4*)&g_PVp[(size_t)p*Nn*Fd + t4];
        s[0] += a.x; s[1] += a.y; s[2] += a.z; s[3] += a.w;
    }
    float4 u; float* up = &u.x;
    __nv_bfloat16 hi4[4], lo4[4];
    #pragma unroll
    for (int l = 0; l < 4; l++) {
        float x = s[l] > 0.f ? s[l] : expm1f(s[l]);
        up[l] = x;
        hi4[l] = __float2bfloat16(x);
        lo4[l] = __float2bfloat16(x - __bfloat162float(hi4[l]));
    }
    *(float4*)&g_U[t4] = u;
    *(float4*)&outU[t4] = u;
    *(uint2*)&g_Uhi[t4] = *(uint2*)hi4;
    *(uint2*)&g_Ulo[t4] = *(uint2*)lo4;
}

// ---------------- HMMA GEMM: sim = U U^T (upper triangle), fused conn epilogue + LN partials ----------------
__global__ void __launch_bounds__(256) sim_mma(const float* __restrict__ dist,
                                               const float* __restrict__ deg) {
    int t = blockIdx.x;
    int tbi = 0;
    while (t >= 16 - tbi) { t -= 16 - tbi; tbi++; }
    int tbj = tbi + t;
    int bi = tbi*128, bj = tbj*128;

    extern __shared__ __align__(128) char smem[];
    uint32_t sb = smem_u32(smem);
    const int tid = threadIdx.x, lane = tid & 31, wid = tid >> 5;
    const int mbase = (wid & 3)*32, nbase = (wid >> 2)*64;
    const int NT = Fd/BK;
    const int row = tid >> 1, ch = tid & 1;

    float acc[2][8][4] = {};
    uint4 pA0[2], pA1[2], pB0[2], pB1[2];
    gload2(pA0, g_Uhi, Fd, bi+row, ch*16);
    gload2(pA1, g_Ulo, Fd, bi+row, ch*16);
    gload2(pB0, g_Uhi, Fd, bj+row, ch*16);
    gload2(pB1, g_Ulo, Fd, bj+row, ch*16);
    sstore2(smem, OFF_AHI, row, ch, pA0);
    sstore2(smem, OFF_ALO, row, ch, pA1);
    sstore2(smem, OFF_BHI, row, ch, pB0);
    sstore2(smem, OFF_BLO, row, ch, pB1);
    __syncthreads();

    for (int kt = 0; kt < NT; kt++) {
        int cur = kt & 1, nxt = cur ^ 1;
        if (kt + 1 < NT) {
            int k0 = (kt+1)*BK + ch*16;
            gload2(pA0, g_Uhi, Fd, bi+row, k0);
            gload2(pA1, g_Ulo, Fd, bi+row, k0);
            gload2(pB0, g_Uhi, Fd, bj+row, k0);
            gload2(pB1, g_Ulo, Fd, bj+row, k0);
        }
        mma_compute(sb + cur*STAGE_B, mbase, nbase, lane, acc);
        if (kt + 1 < NT) {
            sstore2(smem, nxt*STAGE_B + OFF_AHI, row, ch, pA0);
            sstore2(smem, nxt*STAGE_B + OFF_ALO, row, ch, pA1);
            sstore2(smem, nxt*STAGE_B + OFF_BHI, row, ch, pB0);
            sstore2(smem, nxt*STAGE_B + OFF_BLO, row, ch, pB1);
        }
        __syncthreads();
    }

    // stage sigmoid(sim) into smem [128][129] floats
    float* st = (float*)smem;
    #pragma unroll
    for (int mt = 0; mt < 2; mt++)
        #pragma unroll
        for (int nt = 0; nt < 8; nt++) {
            int r0 = mbase + mt*16 + (lane >> 2);
            int c0 = nbase + nt*8 + (lane & 3)*2;
            st[r0*129 + c0]       = 1.f / (1.f + __expf(-acc[mt][nt][0]));
            st[r0*129 + c0 + 1]   = 1.f / (1.f + __expf(-acc[mt][nt][1]));
            st[(r0+8)*129 + c0]   = 1.f / (1.f + __expf(-acc[mt][nt][2]));
            st[(r0+8)*129 + c0+1] = 1.f / (1.f + __expf(-acc[mt][nt][3]));
        }
    __syncthreads();
    // direct block C[bi+row, bj+col]; LN partials for (colblk=tbj, rows bi..)
    #pragma unroll
    for (int rep = 0; rep < 8; rep++) {
        int lin = rep*256 + tid;
        int rr = lin >> 4;
        int cb = (lin & 15) << 3;
        size_t idx = (size_t)(bi + rr)*Nn + bj + cb;
        float4 d0 = *(const float4*)&dist[idx];
        float4 d1 = *(const float4*)&dist[idx + 4];
        float4 m0 = *(const float4*)&deg[idx];
        float4 m1 = *(const float4*)&deg[idx + 4];
        const float* sr = &st[rr*129 + cb];
        float4 o0 = make_float4(sr[0]*(-d0.x)*m0.x, sr[1]*(-d0.y)*m0.y,
                                sr[2]*(-d0.z)*m0.z, sr[3]*(-d0.w)*m0.w);
        float4 o1 = make_float4(sr[4]*(-d1.x)*m1.x, sr[5]*(-d1.y)*m1.y,
                                sr[6]*(-d1.z)*m1.z, sr[7]*(-d1.w)*m1.w);
        *(float4*)&g_C[idx]     = o0;
        *(float4*)&g_C[idx + 4] = o1;
        float s  = ((o0.x+o0.y)+(o0.z+o0.w)) + ((o1.x+o1.y)+(o1.z+o1.w));
        float s2 = fmaf(o0.x,o0.x, fmaf(o0.y,o0.y, fmaf(o0.z,o0.z, fmaf(o0.w,o0.w,
                   fmaf(o1.x,o1.x, fmaf(o1.y,o1.y, fmaf(o1.z,o1.z, o1.w*o1.w)))))));
        #pragma unroll
        for (int off = 8; off > 0; off >>= 1) {
            s  += __shfl_down_sync(0xffffffffu, s,  off, 16);
            s2 += __shfl_down_sync(0xffffffffu, s2, off, 16);
        }
        if ((tid & 15) == 0) {
            g_Sp[tbj*Nn + bi + rr]  = s;
            g_S2p[tbj*Nn + bi + rr] = s2;
        }
    }
    // mirror block C[bj+row, bi+col]; LN partials for (colblk=tbi, rows bj..)
    if (tbi != tbj) {
        #pragma unroll
        for (int rep = 0; rep < 8; rep++) {
            int lin = rep*256 + tid;
            int rr = lin >> 4;
            int cb = (lin & 15) << 3;
            size_t idx = (size_t)(bj + rr)*Nn + bi + cb;
            float4 d0 = *(const float4*)&dist[idx];
            float4 d1 = *(const float4*)&dist[idx + 4];
            float4 m0 = *(const float4*)&deg[idx];
            float4 m1 = *(const float4*)&deg[idx + 4];
            float sv[8];
            #pragma unroll
            for (int k = 0; k < 8; k++) sv[k] = st[(cb + k)*129 + rr];
            float4 o0 = make_float4(sv[0]*(-d0.x)*m0.x, sv[1]*(-d0.y)*m0.y,
                                    sv[2]*(-d0.z)*m0.z, sv[3]*(-d0.w)*m0.w);
            float4 o1 = make_float4(sv[4]*(-d1.x)*m1.x, sv[5]*(-d1.y)*m1.y,
                                    sv[6]*(-d1.z)*m1.z, sv[7]*(-d1.w)*m1.w);
            *(float4*)&g_C[idx]     = o0;
            *(float4*)&g_C[idx + 4] = o1;
            float s  = ((o0.x+o0.y)+(o0.z+o0.w)) + ((o1.x+o1.y)+(o1.z+o1.w));
            float s2 = fmaf(o0.x,o0.x, fmaf(o0.y,o0.y, fmaf(o0.z,o0.z, fmaf(o0.w,o0.w,
                       fmaf(o1.x,o1.x, fmaf(o1.y,o1.y, fmaf(o1.z,o1.z, o1.w*o1.w)))))));
            #pragma unroll
            for (int off = 8; off > 0; off >>= 1) {
                s  += __shfl_down_sync(0xffffffffu, s,  off, 16);
                s2 += __shfl_down_sync(0xffffffffu, s2, off, 16);
            }
            if ((tid & 15) == 0) {
                g_Sp[tbi*Nn + bj + rr]  = s;
                g_S2p[tbi*Nn + bj + rr] = s2;
            }
        }
    }
}

// ---------------- finish LN stats from partials ----------------
__global__ void rn_stats2_kernel() {
    int i = blockIdx.x*256 + threadIdx.x;   // < Nn
    float s = 0.f, s2 = 0.f;
    #pragma unroll
    for (int c = 0; c < 16; c++) {
        s  += g_Sp[c*Nn + i];
        s2 += g_S2p[c*Nn + i];
    }
    float mean = s * (1.f/Nn);
    float var  = s2 * (1.f/Nn) - mean*mean;
    g_mu[i] = mean;
    g_rs[i] = rsqrtf(var + 1e-5f);
}

// ---------------- out = norm(C) + norm(C)^T ----------------
__global__ void symadd_kernel(float* __restrict__ outC) {
    __shared__ float tsh[32][33];
    int bx = blockIdx.x, by = blockIdx.y;
    int tx = threadIdx.x, ty = threadIdx.y;
    #pragma unroll
    for (int r = 0; r < 32; r += 8)
        tsh[ty + r][tx] = g_C[(size_t)(bx*32 + ty + r)*Nn + by*32 + tx];
    int j = bx*32 + tx;
    float muj = g_mu[j], rsj = g_rs[j];
    __syncthreads();
    #pragma unroll
    for (int r = 0; r < 32; r += 8) {
        int i = by*32 + ty + r;
        float mui = g_mu[i], rsi = g_rs[i];
        float cij = g_C[(size_t)i*Nn + j];
        float cji = tsh[tx][ty + r];
        outC[(size_t)i*Nn + j] = (cij - mui)*rsi + (cji - muj)*rsj;
    }
}

extern "C" void kernel_launch(void* const* d_in, const int* in_sizes, int n_in,
                              void* d_out, int out_size) {
    const float* X    = (const float*)d_in[0];
    const float* dist = (const float*)d_in[1];
    const float* bond = (const float*)d_in[2];
    const float* deg  = (const float*)d_in[4];
    const float* Wq   = (const float*)d_in[5];
    const float* Wk   = (const float*)d_in[6];
    const float* Wv   = (const float*)d_in[7];
    const float* wb   = (const float*)d_in[8];
    const float* wbc  = (const float*)d_in[9];
    const float* wg   = (const float*)d_in[10];
    float* out  = (float*)d_out;
    float* outU = out;
    float* outC = out + Nn*Fd;

    cudaFuncSetAttribute(gemm_pv_mma, cudaFuncAttributeMaxDynamicSharedMemorySize, SMEM_MMA);
    cudaFuncSetAttribute(sim_mma, cudaFuncAttributeMaxDynamicSharedMemorySize, SMEM_MMA);

    float* g_v = g_U;   // v lives in g_U until pv_reduce overwrites it

    qk_kernel<<<Nn, 256>>>(X, Wq, Wk);
    gemm_v_kernel<<<dim3(Fd/64, Nn/64), 256>>>(X, Wv, g_v);
    vt_kernel<<<dim3(Nn/32, Fd/32), dim3(32, 8)>>>(g_v);
    colz_kernel<<<dim3(2, IC), 256>>>(bond, dist, deg, wb, wbc, wg);
    zred1_kernel<<<dim3(NH/256, 16), 256>>>();
    zred2_kernel<<<NH/256, 256>>>();
    attnp_kernel<<<dim3(2, IC), 256>>>(bond, dist, deg, wb, wbc, wg);
    gemm_pv_mma<<<dim3(Fd/128, Nn/128, SK), 256, SMEM_MMA>>>();
    pv_reduce_kernel<<<Nn*Fd/1024, 256>>>(outU);
    sim_mma<<<136, 256, SMEM_MMA>>>(dist, deg);
    rn_stats2_kernel<<<Nn/256, 256>>>();
    symadd_kernel<<<dim3(Nn/32, Nn/32), dim3(32, 8)>>>(outC);
}

// round 7
// speedup vs baseline: 4.4824x; 1.2483x over previous
#include <cuda_runtime.h>
#include <cuda_bf16.h>
#include <math.h>
#include <stdint.h>

#define Nn 2048
#define Fd 256
#define Hh 8
#define NH (Nn*Hh)
#define IC 256           // i-chunks for deterministic column-sum partials
#define RPC (Nn/IC)      // 8 rows per chunk
#define SK 8             // split-K for P@v
#define BK 32

// ---------------- scratch (static device globals) ----------------
__device__ float g_eq1[NH];
__device__ float g_eq2[NH];
__device__ float g_rZ[NH];
__device__ float g_P[Nn*Nn];                           // Z-partials scratch
__device__ __align__(16) __nv_bfloat16 g_Phi[Nn*Nn];   // P hi [N][N]
__device__ __align__(16) __nv_bfloat16 g_Plo[Nn*Nn];   // P lo
__device__ __align__(16) __nv_bfloat16 g_vThi[Fd*Nn];  // v^T hi [F][N]
__device__ __align__(16) __nv_bfloat16 g_vTlo[Fd*Nn];
__device__ float g_PVp[SK*Nn*Fd];                      // split-K partials; also zred scratch
__device__ __align__(16) __nv_bfloat16 g_Uhi[Nn*Fd];   // U hi [N][F]
__device__ __align__(16) __nv_bfloat16 g_Ulo[Nn*Fd];
__device__ float g_C[Nn*Nn];
__device__ float g_Sp[16*Nn];                          // LN row-sum partials per col-block
__device__ float g_S2p[16*Nn];
__device__ float g_mu[Nn];
__device__ float g_rs[Nn];

// ---------------- mma helpers ----------------
__device__ __forceinline__ uint32_t smem_u32(const void* p) {
    uint32_t a;
    asm("{ .reg .u64 t; cvta.to.shared.u64 t, %1; cvt.u32.u64 %0, t; }" : "=r"(a) : "l"(p));
    return a;
}
__device__ __forceinline__ void ldm4(uint32_t* r, uint32_t addr) {
    asm volatile("ldmatrix.sync.aligned.m8n8.x4.shared.b16 {%0,%1,%2,%3}, [%4];"
        : "=r"(r[0]), "=r"(r[1]), "=r"(r[2]), "=r"(r[3]) : "r"(addr));
}
__device__ __forceinline__ void mma16816(float* c, const uint32_t* a, uint32_t b0, uint32_t b1) {
    asm volatile("mma.sync.aligned.m16n8k16.row.col.f32.bf16.bf16.f32 "
        "{%0,%1,%2,%3}, {%4,%5,%6,%7}, {%8,%9}, {%0,%1,%2,%3};"
        : "+f"(c[0]), "+f"(c[1]), "+f"(c[2]), "+f"(c[3])
        : "r"(a[0]), "r"(a[1]), "r"(a[2]), "r"(a[3]), "r"(b0), "r"(b1));
}

#define TILE_B   (128*80)
#define OFF_AHI  0
#define OFF_ALO  (TILE_B)
#define OFF_BHI  (2*TILE_B)
#define OFF_BLO  (3*TILE_B)
#define STAGE_B  (4*TILE_B)
#define SMEM_MMA (2*STAGE_B)      // 81920 (>= 128*129*4 staging for sim)

__device__ __forceinline__ void gload2(uint4* d, const __nv_bfloat16* src, int strid, int r, int k) {
    const uint4* p = (const uint4*)(src + (size_t)r*strid + k);
    d[0] = p[0]; d[1] = p[1];
}
__device__ __forceinline__ void sstore2(char* smem, int off, int row, int ch, const uint4* d) {
    uint4* p = (uint4*)(smem + off + row*80 + ch*32);
    p[0] = d[0]; p[1] = d[1];
}

__device__ __forceinline__ void mma_compute(uint32_t base, int mbase, int nbase,
                                            int lane, float acc[2][8][4]) {
    #pragma unroll
    for (int kk = 0; kk < 2; kk++) {
        uint32_t rsel = lane & 15;
        uint32_t csel = (kk*16 + ((lane >> 4) << 3)) * 2;
        uint32_t ah[2][4], al[2][4], bh[4][4], bl[4][4];
        #pragma unroll
        for (int mt = 0; mt < 2; mt++) {
            uint32_t ro = (mbase + mt*16 + rsel)*80 + csel;
            ldm4(ah[mt], base + OFF_AHI + ro);
            ldm4(al[mt], base + OFF_ALO + ro);
        }
        #pragma unroll
        for (int ck = 0; ck < 4; ck++) {
            uint32_t ro = (nbase + ck*16 + rsel)*80 + csel;
            ldm4(bh[ck], base + OFF_BHI + ro);
            ldm4(bl[ck], base + OFF_BLO + ro);
        }
        #pragma unroll
        for (int mt = 0; mt < 2; mt++)
            #pragma unroll
            for (int nt = 0; nt < 8; nt++) {
                int ck = nt >> 1, pr = nt & 1;
                mma16816(acc[mt][nt], ah[mt], bh[ck][pr], bh[ck][2+pr]);
                mma16816(acc[mt][nt], ah[mt], bl[ck][pr], bl[ck][2+pr]);
                mma16816(acc[mt][nt], al[mt], bh[ck][pr], bh[ck][2+pr]);
            }
    }
}

// ---------------- qk projection ----------------
__global__ void qk_kernel(const float* __restrict__ X, const float* __restrict__ Wq,
                          const float* __restrict__ Wk) {
    __shared__ float xs[Fd];
    int i = blockIdx.x;
    int t = threadIdx.x;
    xs[t] = X[i*Fd + t];
    __syncthreads();
    int w = t >> 5, lane = t & 31;
    float qa = 0.f, ka = 0.f;
    #pragma unroll
    for (int c = lane; c < Fd; c += 32) {
        float x = xs[c];
        qa = fmaf(x, Wq[c*Hh + w], qa);
        ka = fmaf(x, Wk[c*Hh + w], ka);
    }
    #pragma unroll
    for (int o = 16; o > 0; o >>= 1) {
        qa += __shfl_down_sync(0xffffffffu, qa, o);
        ka += __shfl_down_sync(0xffffffffu, ka, o);
    }
    if (lane == 0) {
        float qk = (qa + ka) * (0.0625f * 0.3535533905932738f);
        g_eq1[i*Hh + w] = __expf(qk);
        g_eq2[i*Hh + w] = __expf(0.2f * qk);
    }
}

// ---------------- v = X @ Wv / 16, fused transpose + hi/lo split ----------------
__global__ void gemm_v_kernel(const float* __restrict__ X, const float* __restrict__ Wv) {
    __shared__ float As[16][64];
    __shared__ float Bs[16][64];
    __shared__ float vs[64][65];
    int tid = threadIdx.x;
    int bi = blockIdx.y * 64;   // node block
    int bc = blockIdx.x * 64;   // feature block
    int arow = tid >> 2,  acol = (tid & 3)  << 2;
    int brow = tid >> 4,  bcol = (tid & 15) << 2;
    int ty   = tid >> 4,  tx   = tid & 15;
    float acc[4][4] = {};
    for (int k0 = 0; k0 < Fd; k0 += 16) {
        float4 a = *(const float4*)&X[(size_t)(bi + arow)*Fd + k0 + acol];
        float4 b = *(const float4*)&Wv[(size_t)(k0 + brow)*Fd + bc + bcol];
        As[acol+0][arow] = a.x; As[acol+1][arow] = a.y;
        As[acol+2][arow] = a.z; As[acol+3][arow] = a.w;
        *(float4*)&Bs[brow][bcol] = b;
        __syncthreads();
        #pragma unroll
        for (int kk = 0; kk < 16; kk++) {
            float ar[4], br[4];
            *(float4*)ar = *(const float4*)&As[kk][ty*4];
            *(float4*)br = *(const float4*)&Bs[kk][tx*4];
            #pragma unroll
            for (int r = 0; r < 4; r++)
                #pragma unroll
                for (int c = 0; c < 4; c++)
                    acc[r][c] = fmaf(ar[r], br[c], acc[r][c]);
        }
        __syncthreads();
    }
    // stage tile (node-local row, feature-local col)
    #pragma unroll
    for (int r = 0; r < 4; r++)
        #pragma unroll
        for (int c = 0; c < 4; c++)
            vs[ty*4 + r][tx*4 + c] = acc[r][c] * 0.0625f;
    __syncthreads();
    // transposed hi/lo write: vT[f][i]
    #pragma unroll
    for (int r = 0; r < 4; r++) {
        int wf = ty*4 + r;                 // local feature
        __nv_bfloat16 hi4[4], lo4[4];
        #pragma unroll
        for (int c = 0; c < 4; c++) {
            float x = vs[tx*4 + c][wf];
            hi4[c] = __float2bfloat16(x);
            lo4[c] = __float2bfloat16(x - __bfloat162float(hi4[c]));
        }
        size_t off = (size_t)(bc + wf)*Nn + bi + tx*4;
        *(uint2*)&g_vThi[off] = *(uint2*)hi4;
        *(uint2*)&g_vTlo[off] = *(uint2*)lo4;
    }
}

// ---------------- pass B: column softmax denominators ----------------
__global__ void colz_kernel(const float* __restrict__ bond, const float* __restrict__ dist,
                            const float* __restrict__ deg, const float* __restrict__ pwb,
                            const float* __restrict__ pwbc, const float* __restrict__ pwg) {
    __shared__ float2 se[RPC*Hh];
    int tid = threadIdx.x;
    int j = blockIdx.x*512 + tid*4;
    int i0 = blockIdx.y*RPC;
    if (tid < RPC*Hh) se[tid] = make_float2(g_eq1[i0*Hh + tid], g_eq2[i0*Hh + tid]);
    __syncthreads();
    float cb = pwb[0]*pwbc[0], wg = pwg[0];
    float z[4][Hh];
    #pragma unroll
    for (int l = 0; l < 4; l++)
        #pragma unroll
        for (int h = 0; h < Hh; h++) z[l][h] = 0.f;
    #pragma unroll
    for (int ii = 0; ii < RPC; ii++) {
        size_t idx = (size_t)(i0+ii)*Nn + j;
        float4 dg = *(const float4*)&deg[idx];
        float4 bd = *(const float4*)&bond[idx];
        float4 ds = *(const float4*)&dist[idx];
        const float* dgp = &dg.x; const float* bdp = &bd.x; const float* dsp = &ds.x;
        float E1[4], E2[4];
        #pragma unroll
        for (int l = 0; l < 4; l++) {
            float e = fmaf(bdp[l], cb, dsp[l]*wg);
            float f = dgp[l] > 0.f ? 1.f : 0.f;
            float e2 = __expf(0.2f*e) * f;
            float e2sq = e2*e2;
            E2[l] = e2;
            E1[l] = e2sq*e2sq*e2;   // exp(e)*f (f in {0,1})
        }
        #pragma unroll
        for (int h = 0; h < Hh; h++) {
            float2 s12 = se[ii*Hh + h];
            #pragma unroll
            for (int l = 0; l < 4; l++)
                z[l][h] += fmaxf(s12.x*E1[l], s12.y*E2[l]);
        }
    }
    float* zp = &g_P[(size_t)blockIdx.y*NH + (size_t)j*Hh];
    #pragma unroll
    for (int l = 0; l < 4; l++)
        #pragma unroll
        for (int h = 0; h < Hh; h += 4)
            *(float4*)&zp[l*Hh + h] = make_float4(z[l][h], z[l][h+1], z[l][h+2], z[l][h+3]);
}

// ---------------- zred: two-stage deterministic reduction ----------------
__global__ void zred1_kernel() {
    int t = blockIdx.x*256 + threadIdx.x;   // < NH
    int c0 = blockIdx.y*16;
    float s = 0.f;
    #pragma unroll
    for (int c = 0; c < 16; c++) s += g_P[(size_t)(c0 + c)*NH + t];
    g_PVp[(size_t)blockIdx.y*NH + t] = s;
}
__global__ void zred2_kernel() {
    int t = blockIdx.x*256 + threadIdx.x;   // < NH
    float s = 0.f;
    #pragma unroll
    for (int c = 0; c < 16; c++) s += g_PVp[(size_t)c*NH + t];
    g_rZ[t] = 1.f / s;
}

// ---------------- pass C: P -> bf16 hi/lo ----------------
__global__ void attnp_kernel(const float* __restrict__ bond, const float* __restrict__ dist,
                             const float* __restrict__ deg, const float* __restrict__ pwb,
                             const float* __restrict__ pwbc, const float* __restrict__ pwg) {
    __shared__ float2 se[RPC*Hh];
    int tid = threadIdx.x;
    int j = blockIdx.x*512 + tid*4;
    int i0 = blockIdx.y*RPC;
    if (tid < RPC*Hh) se[tid] = make_float2(g_eq1[i0*Hh + tid], g_eq2[i0*Hh + tid]);
    __syncthreads();
    float rz[4][Hh];
    #pragma unroll
    for (int l = 0; l < 4; l++)
        #pragma unroll
        for (int h = 0; h < Hh; h += 4)
            *(float4*)&rz[l][h] = *(const float4*)&g_rZ[(size_t)(j+l)*Hh + h];
    float cb = pwb[0]*pwbc[0], wg = pwg[0];
    #pragma unroll
    for (int ii = 0; ii < RPC; ii++) {
        size_t idx = (size_t)(i0+ii)*Nn + j;
        float4 dg = *(const float4*)&deg[idx];
        float4 bd = *(const float4*)&bond[idx];
        float4 ds = *(const float4*)&dist[idx];
        const float* dgp = &dg.x; const float* bdp = &bd.x; const float* dsp = &ds.x;
        float p[4] = {0.f, 0.f, 0.f, 0.f};
        float E1[4], E2[4];
        #pragma unroll
        for (int l = 0; l < 4; l++) {
            float e = fmaf(bdp[l], cb, dsp[l]*wg);
            float f = dgp[l] > 0.f ? 1.f : 0.f;
            float e2 = __expf(0.2f*e) * f;
            float e2sq = e2*e2;
            E2[l] = e2;
            E1[l] = e2sq*e2sq*e2;
        }
        #pragma unroll
        for (int h = 0; h < Hh; h++) {
            float2 s12 = se[ii*Hh + h];
            #pragma unroll
            for (int l = 0; l < 4; l++)
                p[l] = fmaf(fmaxf(s12.x*E1[l], s12.y*E2[l]), rz[l][h], p[l]);
        }
        __nv_bfloat16 hi4[4], lo4[4];
        #pragma unroll
        for (int l = 0; l < 4; l++) {
            float pv = p[l] * 0.125f;
            hi4[l] = __float2bfloat16(pv);
            lo4[l] = __float2bfloat16(pv - __bfloat162float(hi4[l]));
        }
        *(uint2*)&g_Phi[idx] = *(uint2*)hi4;
        *(uint2*)&g_Plo[idx] = *(uint2*)lo4;
    }
}

// ---------------- HMMA GEMM: P @ v split-K partials ----------------
__global__ void __launch_bounds__(256) gemm_pv_mma() {
    extern __shared__ __align__(128) char smem[];
    uint32_t sb = smem_u32(smem);
    const int tid = threadIdx.x, lane = tid & 31, wid = tid >> 5;
    const int mbase = (wid & 3)*32, nbase = (wid >> 2)*64;
    const int bi = blockIdx.y*128, bc = blockIdx.x*128;
    const int ks = blockIdx.z*(Nn/SK);
    const int NT = (Nn/SK)/BK;   // 8
    const int row = tid >> 1, ch = tid & 1;

    float acc[2][8][4] = {};
    uint4 pA0[2], pA1[2], pB0[2], pB1[2];
    gload2(pA0, g_Phi,  Nn, bi+row, ks + ch*16);
    gload2(pA1, g_Plo,  Nn, bi+row, ks + ch*16);
    gload2(pB0, g_vThi, Nn, bc+row, ks + ch*16);
    gload2(pB1, g_vTlo, Nn, bc+row, ks + ch*16);
    sstore2(smem, OFF_AHI, row, ch, pA0);
    sstore2(smem, OFF_ALO, row, ch, pA1);
    sstore2(smem, OFF_BHI, row, ch, pB0);
    sstore2(smem, OFF_BLO, row, ch, pB1);
    __syncthreads();

    for (int kt = 0; kt < NT; kt++) {
        int cur = kt & 1, nxt = cur ^ 1;
        if (kt + 1 < NT) {
            int k0 = ks + (kt+1)*BK + ch*16;
            gload2(pA0, g_Phi,  Nn, bi+row, k0);
            gload2(pA1, g_Plo,  Nn, bi+row, k0);
            gload2(pB0, g_vThi, Nn, bc+row, k0);
            gload2(pB1, g_vTlo, Nn, bc+row, k0);
        }
        mma_compute(sb + cur*STAGE_B, mbase, nbase, lane, acc);
        if (kt + 1 < NT) {
            sstore2(smem, nxt*STAGE_B + OFF_AHI, row, ch, pA0);
            sstore2(smem, nxt*STAGE_B + OFF_ALO, row, ch, pA1);
            sstore2(smem, nxt*STAGE_B + OFF_BHI, row, ch, pB0);
            sstore2(smem, nxt*STAGE_B + OFF_BLO, row, ch, pB1);
        }
        __syncthreads();
    }
    float* dst = &g_PVp[(size_t)blockIdx.z*Nn*Fd];
    #pragma unroll
    for (int mt = 0; mt < 2; mt++)
        #pragma unroll
        for (int nt = 0; nt < 8; nt++) {
            int r0 = bi + mbase + mt*16 + (lane >> 2);
            int c0 = bc + nbase + nt*8 + (lane & 3)*2;
            *(float2*)&dst[(size_t)r0*Fd + c0]     = make_float2(acc[mt][nt][0], acc[mt][nt][1]);
            *(float2*)&dst[(size_t)(r0+8)*Fd + c0] = make_float2(acc[mt][nt][2], acc[mt][nt][3]);
        }
}

// reduce split-K + elu -> outU + U hi/lo bf16
__global__ void pv_reduce_kernel(float* __restrict__ outU) {
    size_t t4 = ((size_t)blockIdx.x*256 + threadIdx.x) * 4;
    float s[4] = {0.f, 0.f, 0.f, 0.f};
    #pragma unroll
    for (int p = 0; p < SK; p++) {
        float4 a = *(const float4*)&g_PVp[(size_t)p*Nn*Fd + t4];
        s[0] += a.x; s[1] += a.y; s[2] += a.z; s[3] += a.w;
    }
    float4 u; float* up = &u.x;
    __nv_bfloat16 hi4[4], lo4[4];
    #pragma unroll
    for (int l = 0; l < 4; l++) {
        float x = s[l] > 0.f ? s[l] : expm1f(s[l]);
        up[l] = x;
        hi4[l] = __float2bfloat16(x);
        lo4[l] = __float2bfloat16(x - __bfloat162float(hi4[l]));
    }
    *(float4*)&outU[t4] = u;
    *(uint2*)&g_Uhi[t4] = *(uint2*)hi4;
    *(uint2*)&g_Ulo[t4] = *(uint2*)lo4;
}

// ---------------- HMMA GEMM: sim = U U^T (upper triangle), fused conn epilogue + LN partials ----------------
__global__ void __launch_bounds__(256) sim_mma(const float* __restrict__ dist,
                                               const float* __restrict__ deg) {
    int t = blockIdx.x;
    int tbi = 0;
    while (t >= 16 - tbi) { t -= 16 - tbi; tbi++; }
    int tbj = tbi + t;
    int bi = tbi*128, bj = tbj*128;

    extern __shared__ __align__(128) char smem[];
    uint32_t sb = smem_u32(smem);
    const int tid = threadIdx.x, lane = tid & 31, wid = tid >> 5;
    const int mbase = (wid & 3)*32, nbase = (wid >> 2)*64;
    const int NT = Fd/BK;
    const int row = tid >> 1, ch = tid & 1;

    float acc[2][8][4] = {};
    uint4 pA0[2], pA1[2], pB0[2], pB1[2];
    gload2(pA0, g_Uhi, Fd, bi+row, ch*16);
    gload2(pA1, g_Ulo, Fd, bi+row, ch*16);
    gload2(pB0, g_Uhi, Fd, bj+row, ch*16);
    gload2(pB1, g_Ulo, Fd, bj+row, ch*16);
    sstore2(smem, OFF_AHI, row, ch, pA0);
    sstore2(smem, OFF_ALO, row, ch, pA1);
    sstore2(smem, OFF_BHI, row, ch, pB0);
    sstore2(smem, OFF_BLO, row, ch, pB1);
    __syncthreads();

    for (int kt = 0; kt < NT; kt++) {
        int cur = kt & 1, nxt = cur ^ 1;
        if (kt + 1 < NT) {
            int k0 = (kt+1)*BK + ch*16;
            gload2(pA0, g_Uhi, Fd, bi+row, k0);
            gload2(pA1, g_Ulo, Fd, bi+row, k0);
            gload2(pB0, g_Uhi, Fd, bj+row, k0);
            gload2(pB1, g_Ulo, Fd, bj+row, k0);
        }
        mma_compute(sb + cur*STAGE_B, mbase, nbase, lane, acc);
        if (kt + 1 < NT) {
            sstore2(smem, nxt*STAGE_B + OFF_AHI, row, ch, pA0);
            sstore2(smem, nxt*STAGE_B + OFF_ALO, row, ch, pA1);
            sstore2(smem, nxt*STAGE_B + OFF_BHI, row, ch, pB0);
            sstore2(smem, nxt*STAGE_B + OFF_BLO, row, ch, pB1);
        }
        __syncthreads();
    }

    // stage sigmoid(sim) into smem [128][129] floats
    float* st = (float*)smem;
    #pragma unroll
    for (int mt = 0; mt < 2; mt++)
        #pragma unroll
        for (int nt = 0; nt < 8; nt++) {
            int r0 = mbase + mt*16 + (lane >> 2);
            int c0 = nbase + nt*8 + (lane & 3)*2;
            st[r0*129 + c0]       = 1.f / (1.f + __expf(-acc[mt][nt][0]));
            st[r0*129 + c0 + 1]   = 1.f / (1.f + __expf(-acc[mt][nt][1]));
            st[(r0+8)*129 + c0]   = 1.f / (1.f + __expf(-acc[mt][nt][2]));
            st[(r0+8)*129 + c0+1] = 1.f / (1.f + __expf(-acc[mt][nt][3]));
        }
    __syncthreads();
    // direct block C[bi+row, bj+col]; LN partials for (colblk=tbj, rows bi..)
    #pragma unroll
    for (int rep = 0; rep < 8; rep++) {
        int lin = rep*256 + tid;
        int rr = lin >> 4;
        int cb = (lin & 15) << 3;
        size_t idx = (size_t)(bi + rr)*Nn + bj + cb;
        float4 d0 = *(const float4*)&dist[idx];
        float4 d1 = *(const float4*)&dist[idx + 4];
        float4 m0 = *(const float4*)&deg[idx];
        float4 m1 = *(const float4*)&deg[idx + 4];
        const float* sr = &st[rr*129 + cb];
        float4 o0 = make_float4(sr[0]*(-d0.x)*m0.x, sr[1]*(-d0.y)*m0.y,
                                sr[2]*(-d0.z)*m0.z, sr[3]*(-d0.w)*m0.w);
        float4 o1 = make_float4(sr[4]*(-d1.x)*m1.x, sr[5]*(-d1.y)*m1.y,
                                sr[6]*(-d1.z)*m1.z, sr[7]*(-d1.w)*m1.w);
        *(float4*)&g_C[idx]     = o0;
        *(float4*)&g_C[idx + 4] = o1;
        float s  = ((o0.x+o0.y)+(o0.z+o0.w)) + ((o1.x+o1.y)+(o1.z+o1.w));
        float s2 = fmaf(o0.x,o0.x, fmaf(o0.y,o0.y, fmaf(o0.z,o0.z, fmaf(o0.w,o0.w,
                   fmaf(o1.x,o1.x, fmaf(o1.y,o1.y, fmaf(o1.z,o1.z, o1.w*o1.w)))))));
        #pragma unroll
        for (int off = 8; off > 0; off >>= 1) {
            s  += __shfl_down_sync(0xffffffffu, s,  off, 16);
            s2 += __shfl_down_sync(0xffffffffu, s2, off, 16);
        }
        if ((tid & 15) == 0) {
            g_Sp[tbj*Nn + bi + rr]  = s;
            g_S2p[tbj*Nn + bi + rr] = s2;
        }
    }
    // mirror block C[bj+row, bi+col]; LN partials for (colblk=tbi, rows bj..)
    if (tbi != tbj) {
        #pragma unroll
        for (int rep = 0; rep < 8; rep++) {
            int lin = rep*256 + tid;
            int rr = lin >> 4;
            int cb = (lin & 15) << 3;
            size_t idx = (size_t)(bj + rr)*Nn + bi + cb;
            float4 d0 = *(const float4*)&dist[idx];
            float4 d1 = *(const float4*)&dist[idx + 4];
            float4 m0 = *(const float4*)&deg[idx];
            float4 m1 = *(const float4*)&deg[idx + 4];
            float sv[8];
            #pragma unroll
            for (int k = 0; k < 8; k++) sv[k] = st[(cb + k)*129 + rr];
            float4 o0 = make_float4(sv[0]*(-d0.x)*m0.x, sv[1]*(-d0.y)*m0.y,
                                    sv[2]*(-d0.z)*m0.z, sv[3]*(-d0.w)*m0.w);
            float4 o1 = make_float4(sv[4]*(-d1.x)*m1.x, sv[5]*(-d1.y)*m1.y,
                                    sv[6]*(-d1.z)*m1.z, sv[7]*(-d1.w)*m1.w);
            *(float4*)&g_C[idx]     = o0;
            *(float4*)&g_C[idx + 4] = o1;
            float s  = ((o0.x+o0.y)+(o0.z+o0.w)) + ((o1.x+o1.y)+(o1.z+o1.w));
            float s2 = fmaf(o0.x,o0.x, fmaf(o0.y,o0.y, fmaf(o0.z,o0.z, fmaf(o0.w,o0.w,
                       fmaf(o1.x,o1.x, fmaf(o1.y,o1.y, fmaf(o1.z,o1.z, o1.w*o1.w)))))));
            #pragma unroll
            for (int off = 8; off > 0; off >>= 1) {
                s  += __shfl_down_sync(0xffffffffu, s,  off, 16);
                s2 += __shfl_down_sync(0xffffffffu, s2, off, 16);
            }
            if ((tid & 15) == 0) {
                g_Sp[tbi*Nn + bj + rr]  = s;
                g_S2p[tbi*Nn + bj + rr] = s2;
            }
        }
    }
}

// ---------------- finish LN stats from partials ----------------
__global__ void rn_stats2_kernel() {
    int i = blockIdx.x*256 + threadIdx.x;   // < Nn
    float s = 0.f, s2 = 0.f;
    #pragma unroll
    for (int c = 0; c < 16; c++) {
        s  += g_Sp[c*Nn + i];
        s2 += g_S2p[c*Nn + i];
    }
    float mean = s * (1.f/Nn);
    float var  = s2 * (1.f/Nn) - mean*mean;
    g_mu[i] = mean;
    g_rs[i] = rsqrtf(var + 1e-5f);
}

// ---------------- out = norm(C) + norm(C)^T ----------------
__global__ void symadd_kernel(float* __restrict__ outC) {
    __shared__ float tsh[32][33];
    int bx = blockIdx.x, by = blockIdx.y;
    int tx = threadIdx.x, ty = threadIdx.y;
    #pragma unroll
    for (int r = 0; r < 32; r += 8)
        tsh[ty + r][tx] = g_C[(size_t)(bx*32 + ty + r)*Nn + by*32 + tx];
    int j = bx*32 + tx;
    float muj = g_mu[j], rsj = g_rs[j];
    __syncthreads();
    #pragma unroll
    for (int r = 0; r < 32; r += 8) {
        int i = by*32 + ty + r;
        float mui = g_mu[i], rsi = g_rs[i];
        float cij = g_C[(size_t)i*Nn + j];
        float cji = tsh[tx][ty + r];
        outC[(size_t)i*Nn + j] = (cij - mui)*rsi + (cji - muj)*rsj;
    }
}

extern "C" void kernel_launch(void* const* d_in, const int* in_sizes, int n_in,
                              void* d_out, int out_size) {
    const float* X    = (const float*)d_in[0];
    const float* dist = (const float*)d_in[1];
    const float* bond = (const float*)d_in[2];
    const float* deg  = (const float*)d_in[4];
    const float* Wq   = (const float*)d_in[5];
    const float* Wk   = (const float*)d_in[6];
    const float* Wv   = (const float*)d_in[7];
    const float* wb   = (const float*)d_in[8];
    const float* wbc  = (const float*)d_in[9];
    const float* wg   = (const float*)d_in[10];
    float* out  = (float*)d_out;
    float* outU = out;
    float* outC = out + Nn*Fd;

    cudaFuncSetAttribute(gemm_pv_mma, cudaFuncAttributeMaxDynamicSharedMemorySize, SMEM_MMA);
    cudaFuncSetAttribute(sim_mma, cudaFuncAttributeMaxDynamicSharedMemorySize, SMEM_MMA);

    qk_kernel<<<Nn, 256>>>(X, Wq, Wk);
    gemm_v_kernel<<<dim3(Fd/64, Nn/64), 256>>>(X, Wv);
    colz_kernel<<<dim3(4, IC), 128>>>(bond, dist, deg, wb, wbc, wg);
    zred1_kernel<<<dim3(NH/256, 16), 256>>>();
    zred2_kernel<<<NH/256, 256>>>();
    attnp_kernel<<<dim3(4, IC), 128>>>(bond, dist, deg, wb, wbc, wg);
    gemm_pv_mma<<<dim3(Fd/128, Nn/128, SK), 256, SMEM_MMA>>>();
    pv_reduce_kernel<<<Nn*Fd/1024, 256>>>(outU);
    sim_mma<<<136, 256, SMEM_MMA>>>(dist, deg);
    rn_stats2_kernel<<<Nn/256, 256>>>();
    symadd_kernel<<<dim3(Nn/32, Nn/32), dim3(32, 8)>>>(outC);
}